// round 11
// baseline (speedup 1.0000x reference)
#include <cuda_runtime.h>
#include <cstdint>
#include <math.h>

// Problem constants: B=16, C=512, L=1024 (32x32), 32 groups, 8 heads, ch=64.
#define NB   16
#define NC   512
#define NL   1024
#define NO3  1536

// Scratch (device globals; no allocation allowed)
__device__ float g_ht [(size_t)NB * NL * NC];    // groupnorm out, [b][l][c], tf32 bits
__device__ float g_qkv[(size_t)NB * NO3 * NL];   // [b][o][l], tf32 bits (Q pre-scaled)
__device__ float g_at [(size_t)NB * NL * NC];    // attention out, [b][l][c], tf32 bits
__device__ float g_wt [(size_t)(NO3 + NC) * NC]; // weights, tf32 bits (Q rows pre-scaled)
__device__ float g_bq [NO3];                     // qkv bias, Q rows pre-scaled

// ===========================================================================
// helpers
// ===========================================================================
__device__ __forceinline__ uint32_t cvt_tf32(float x) {
    uint32_t r;
    asm("cvt.rna.tf32.f32 %0, %1;" : "=r"(r) : "f"(x));
    return r;
}
__device__ __forceinline__ float cvt_tf32f(float x) {
    return __uint_as_float(cvt_tf32(x));
}
__device__ __forceinline__ void mma_tf32(float* d, const uint32_t* a,
                                         const uint32_t* b) {
    asm volatile(
        "mma.sync.aligned.m16n8k8.row.col.f32.tf32.tf32.f32 "
        "{%0,%1,%2,%3}, {%4,%5,%6,%7}, {%8,%9}, {%0,%1,%2,%3};"
        : "+f"(d[0]), "+f"(d[1]), "+f"(d[2]), "+f"(d[3])
        : "r"(a[0]), "r"(a[1]), "r"(a[2]), "r"(a[3]), "r"(b[0]), "r"(b[1]));
}
#define CP_ASYNC16(dst, src) \
    asm volatile("cp.async.cg.shared.global [%0], [%1], 16;" \
                 :: "r"(dst), "l"(src) : "memory")
#define CP_COMMIT() asm volatile("cp.async.commit_group;" ::: "memory")
#define CP_WAIT(n)  asm volatile("cp.async.wait_group %0;" :: "n"(n) : "memory")

__device__ __forceinline__ uint32_t smem_u32(const void* p) {
    uint32_t a;
    asm("{ .reg .u64 t; cvta.to.shared.u64 t, %1; cvt.u32.u64 %0, t; }"
        : "=r"(a) : "l"(p));
    return a;
}

// fast exp on FMA pipe. x <= 0 expected.
__device__ __forceinline__ float fexp(float x) {
    float y = x * 1.4426950408889634f;
    y = fmaxf(y, -125.0f);
    int   e = __float2int_rd(y);
    float f = y - (float)e;
    float p = fmaf(0.0013333558f, f, 0.0096181291f);
    p = fmaf(p, f, 0.0555041087f);
    p = fmaf(p, f, 0.2402264758f);
    p = fmaf(p, f, 0.6931471806f);
    p = fmaf(p, f, 1.0f);
    return p * __int_as_float((e + 127) << 23);
}

// ---------------------------------------------------------------------------
// Pre-round weights to tf32 bits; optionally scale Q rows (row%192 < 64)
// by 0.125 (softmax scale folded into the QKV projection).
// ---------------------------------------------------------------------------
__global__ __launch_bounds__(256) void cvt_w_kernel(const float* __restrict__ src,
                                                    float* __restrict__ dst,
                                                    int n4, int qmode) {
    int i = blockIdx.x * 256 + threadIdx.x;
    if (i < n4) {
        float s = 1.0f;
        if (qmode) {
            int row = i >> 7;                 // NC/4 = 128 float4 per row
            s = ((row % 192) < 64) ? 0.125f : 1.0f;
        }
        float4 v = ((const float4*)src)[i];
        v.x = cvt_tf32f(v.x * s); v.y = cvt_tf32f(v.y * s);
        v.z = cvt_tf32f(v.z * s); v.w = cvt_tf32f(v.w * s);
        ((float4*)dst)[i] = v;
    }
}

__global__ __launch_bounds__(256) void bias_q_kernel(const float* __restrict__ b) {
    int i = blockIdx.x * 256 + threadIdx.x;
    if (i < NO3) g_bq[i] = b[i] * (((i % 192) < 64) ? 0.125f : 1.0f);
}

// ---------------------------------------------------------------------------
// GroupNorm: one block per (batch, group); writes TRANSPOSED h_t[b][l][c],
// tf32-rounded bits. Sector-efficient both ways: loads are 4 c-rows x 8
// consecutive l per instr (4 full 32B sectors); stores are float4 with each
// 4-lane group covering a 64B c-contiguous chunk (full sectors).
// ---------------------------------------------------------------------------
__global__ __launch_bounds__(256) void gn_kernel(const float* __restrict__ x,
                                                 const float* __restrict__ w,
                                                 const float* __restrict__ b) {
    const int blk = blockIdx.x;
    const int bi  = blk >> 5;
    const int g   = blk & 31;
    const int cb  = g << 4;
    const float* xg = x + ((size_t)bi * NC + (size_t)cb) * NL;
    const int tid = threadIdx.x;

    float s = 0.f, s2 = 0.f;
    for (int v = tid; v < 4096; v += 256) {
        float4 q = *(const float4*)(xg + (size_t)v * 4);
        s  += q.x + q.y + q.z + q.w;
        s2 += q.x*q.x + q.y*q.y + q.z*q.z + q.w*q.w;
    }
    #pragma unroll
    for (int d = 16; d; d >>= 1) {
        s  += __shfl_xor_sync(0xffffffffu, s,  d);
        s2 += __shfl_xor_sync(0xffffffffu, s2, d);
    }
    __shared__ float rs[8], rs2[8];
    __shared__ float smean, srstd;
    if ((tid & 31) == 0) { rs[tid >> 5] = s; rs2[tid >> 5] = s2; }
    __syncthreads();
    if (tid == 0) {
        float ts = 0.f, ts2 = 0.f;
        #pragma unroll
        for (int i = 0; i < 8; i++) { ts += rs[i]; ts2 += rs2[i]; }
        float mean = ts * (1.0f / 16384.0f);
        float var  = ts2 * (1.0f / 16384.0f) - mean * mean;
        smean = mean;
        srstd = rsqrtf(var + 1e-5f);
    }
    __syncthreads();
    const float mean = smean, rstd = srstd;

    const int cq = (tid & 3) << 2;        // c-quad within group: 0,4,8,12
    const int lb = tid >> 2;              // l base: 0..63
    float wc[4], bc[4];
    const float* xr[4];
    #pragma unroll
    for (int i = 0; i < 4; i++) {
        wc[i] = w[cb + cq + i] * rstd;
        bc[i] = b[cb + cq + i];
        xr[i] = x + ((size_t)bi * NC + cb + cq + i) * NL;
    }
    float* ob = g_ht + (size_t)bi * NL * NC + cb + cq;
    #pragma unroll
    for (int it = 0; it < 16; it++) {
        const int l = lb + (it << 6);
        float4 o;
        o.x = cvt_tf32f((xr[0][l] - mean) * wc[0] + bc[0]);
        o.y = cvt_tf32f((xr[1][l] - mean) * wc[1] + bc[1]);
        o.z = cvt_tf32f((xr[2][l] - mean) * wc[2] + bc[2]);
        o.w = cvt_tf32f((xr[3][l] - mean) * wc[3] + bc[3]);
        *(float4*)&ob[(size_t)l * NC] = o;
    }
}

// ---------------------------------------------------------------------------
// mma.sync tf32 GEMM + bias. rnd=1 -> outputs tf32-rounded bits. (unchanged)
// ---------------------------------------------------------------------------
#define AST 40
#define TILE_F (128 * AST)
#define GEMM_SMEM (4 * TILE_F * 4)            // 81920 B

__global__ __launch_bounds__(256, 2) void tc_gemm(const float* __restrict__ W,
                                                  const float* __restrict__ bias,
                                                  const float* __restrict__ Xt,
                                                  float* __restrict__ Y,
                                                  int M, int rnd) {
    extern __shared__ float smf[];
    const int tid  = threadIdx.x;
    const int wid  = tid >> 5;
    const int lane = tid & 31;
    const int gid  = lane >> 2;
    const int tig  = lane & 3;
    const int K    = NC;
    const int n_blk = blockIdx.x << 7;
    const int m_blk = blockIdx.y << 7;
    const float* Xb = Xt + (size_t)blockIdx.z * NL * K;
    float*       Yb = Y  + (size_t)blockIdx.z * M * NL;
    const int wm = (wid >> 1) << 5;
    const int wn = (wid & 1) << 6;

    const int lrow = tid >> 3;
    const int lkg  = (tid & 7) << 2;
    const uint32_t sbase = smem_u32(smf);

    float acc[2][8][4];
    #pragma unroll
    for (int a = 0; a < 2; a++)
        #pragma unroll
        for (int b = 0; b < 8; b++)
            #pragma unroll
            for (int c = 0; c < 4; c++) acc[a][b][c] = 0.f;

    const int nkt = K / 32;
    {
        const float* wp = W  + (size_t)(m_blk + lrow) * K + lkg;
        const float* xp = Xb + (size_t)(n_blk + lrow) * K + lkg;
        #pragma unroll
        for (int i = 0; i < 4; i++) {
            uint32_t da = sbase + ((lrow + i * 32) * AST + lkg) * 4;
            uint32_t db = da + TILE_F * 4;
            CP_ASYNC16(da, wp + (size_t)i * 32 * K);
            CP_ASYNC16(db, xp + (size_t)i * 32 * K);
        }
        CP_COMMIT();
    }

    for (int kt = 0; kt < nkt; kt++) {
        const int bf = kt & 1;
        if (kt + 1 < nkt) {
            const int k0 = (kt + 1) << 5;
            const float* wp = W  + (size_t)(m_blk + lrow) * K + k0 + lkg;
            const float* xp = Xb + (size_t)(n_blk + lrow) * K + k0 + lkg;
            uint32_t base = sbase + (((kt + 1) & 1) ? 2 * TILE_F * 4 : 0);
            #pragma unroll
            for (int i = 0; i < 4; i++) {
                uint32_t da = base + ((lrow + i * 32) * AST + lkg) * 4;
                uint32_t db = da + TILE_F * 4;
                CP_ASYNC16(da, wp + (size_t)i * 32 * K);
                CP_ASYNC16(db, xp + (size_t)i * 32 * K);
            }
            CP_COMMIT();
            CP_WAIT(1);
        } else {
            CP_WAIT(0);
        }
        __syncthreads();

        const float* As = smf + (bf ? 2 * TILE_F : 0);
        const float* Bs = As + TILE_F;
        #pragma unroll
        for (int ks = 0; ks < 4; ks++) {
            const int k = ks << 3;
            uint32_t af[2][4];
            #pragma unroll
            for (int mt = 0; mt < 2; mt++) {
                int r0 = wm + (mt << 4) + gid;
                af[mt][0] = __float_as_uint(As[r0 * AST + k + tig]);
                af[mt][1] = __float_as_uint(As[(r0 + 8) * AST + k + tig]);
                af[mt][2] = __float_as_uint(As[r0 * AST + k + tig + 4]);
                af[mt][3] = __float_as_uint(As[(r0 + 8) * AST + k + tig + 4]);
            }
            #pragma unroll
            for (int nt = 0; nt < 8; nt++) {
                int n0 = wn + (nt << 3) + gid;
                uint32_t bfr[2];
                bfr[0] = __float_as_uint(Bs[n0 * AST + k + tig]);
                bfr[1] = __float_as_uint(Bs[n0 * AST + k + tig + 4]);
                mma_tf32(acc[0][nt], af[0], bfr);
                mma_tf32(acc[1][nt], af[1], bfr);
            }
        }
        __syncthreads();
    }

    #pragma unroll
    for (int mt = 0; mt < 2; mt++) {
        int m = m_blk + wm + (mt << 4) + gid;
        float bv0 = bias[m], bv1 = bias[m + 8];
        #pragma unroll
        for (int nt = 0; nt < 8; nt++) {
            int n = n_blk + wn + (nt << 3) + (tig << 1);
            float2 o0, o1;
            if (rnd) {
                o0.x = cvt_tf32f(acc[mt][nt][0] + bv0);
                o0.y = cvt_tf32f(acc[mt][nt][1] + bv0);
                o1.x = cvt_tf32f(acc[mt][nt][2] + bv1);
                o1.y = cvt_tf32f(acc[mt][nt][3] + bv1);
            } else {
                o0.x = acc[mt][nt][0] + bv0; o0.y = acc[mt][nt][1] + bv0;
                o1.x = acc[mt][nt][2] + bv1; o1.y = acc[mt][nt][3] + bv1;
            }
            *(float2*)&Yb[(size_t)m * NL + n]       = o0;
            *(float2*)&Yb[(size_t)(m + 8) * NL + n] = o1;
        }
    }
}

// ---------------------------------------------------------------------------
// Flash attention, mma.sync tf32, register-P, fully async K/V pipeline.
// K tile now has its own stride KST=132: the B-fragment access pattern
// (8nt+gid)*KST + k+tig gives bank (4gid+tig) mod 32 = lane -> conflict-free
// (QST=136 was 2-way conflicted for this pattern).
// smem = Q(64x136) + K(64x132) + V(64x132) = 102,400 B  ->  2 CTAs/SM.
// ---------------------------------------------------------------------------
#define QST 136
#define KST 132
#define VST 132
#define ATTN_SMEM ((64 * QST + 64 * KST + 64 * VST) * 4)

__global__ __launch_bounds__(256, 2) void attn_kernel() {
    extern __shared__ float sm[];
    float* Qs = sm;                     // 64 x 136  [c][t]
    float* Ks = Qs + 64 * QST;          // 64 x 132  [c][s]
    float* Vs = Ks + 64 * KST;          // 64 x 132  [c][s]

    const int head = blockIdx.y;
    const int bi = head >> 3, hh = head & 7;
    const int t0 = blockIdx.x << 7;
    const float* qp = g_qkv + ((size_t)bi * NO3 + (size_t)hh * 192) * NL;
    const float* kp = qp + (size_t)64 * NL;
    const float* vp = kp + (size_t)64 * NL;
    const int tid  = threadIdx.x;
    const int wid  = tid >> 5;
    const int lane = tid & 31;
    const int gid  = lane >> 2;
    const int tig  = lane & 3;
    const int tb   = wid << 4;
    const int r0   = tb + gid, r1 = r0 + 8;

    const int lc   = tid >> 5;            // c row base (8 rows per thread)
    const int lcol = (tid & 31) << 2;     // col within row

    // shuffle source lanes for C-frag -> A-frag remap
    const int Lsrc = (lane & 0x1c) | (tig >> 1);
    const bool hi  = (tig & 1);

    const uint32_t sQ = smem_u32(Qs);
    const uint32_t sK = smem_u32(Ks);
    const uint32_t sV = smem_u32(Vs);

    // async prologue: G0 = Q + K0, G1 = V0
    #pragma unroll
    for (int i = 0; i < 8; i++) {
        int c = lc + i * 8;
        CP_ASYNC16(sQ + (uint32_t)(c * QST + lcol) * 4,
                   qp + (size_t)c * NL + t0 + lcol);
        CP_ASYNC16(sK + (uint32_t)(c * KST + lcol) * 4,
                   kp + (size_t)c * NL + lcol);
    }
    CP_COMMIT();
    #pragma unroll
    for (int i = 0; i < 8; i++) {
        int c = lc + i * 8;
        CP_ASYNC16(sV + (uint32_t)(c * VST + lcol) * 4,
                   vp + (size_t)c * NL + lcol);
    }
    CP_COMMIT();

    float m0 = -1e30f, m1 = -1e30f, l0 = 0.f, l1 = 0.f;
    float oacc[8][4];
    #pragma unroll
    for (int i = 0; i < 8; i++)
        #pragma unroll
        for (int j = 0; j < 4; j++) oacc[i][j] = 0.f;

    for (int it = 0; it < 8; it++) {
        const int s0 = it << 7;
        CP_WAIT(1);        // K(it) (+Q on it=0) landed; V(it) may be in flight
        __syncthreads();

        // --- S = Q^T K
        float sacc[16][4];
        #pragma unroll
        for (int i = 0; i < 16; i++)
            #pragma unroll
            for (int j = 0; j < 4; j++) sacc[i][j] = 0.f;
        #pragma unroll
        for (int ks = 0; ks < 8; ks++) {
            const int k = ks << 3;
            uint32_t af[4];
            af[0] = __float_as_uint(Qs[(k + tig) * QST + tb + gid]);
            af[1] = __float_as_uint(Qs[(k + tig) * QST + tb + gid + 8]);
            af[2] = __float_as_uint(Qs[(k + tig + 4) * QST + tb + gid]);
            af[3] = __float_as_uint(Qs[(k + tig + 4) * QST + tb + gid + 8]);
            #pragma unroll
            for (int nt = 0; nt < 16; nt++) {
                int sc = (nt << 3) + gid;
                uint32_t bfr[2];
                bfr[0] = __float_as_uint(Ks[(k + tig) * KST + sc]);
                bfr[1] = __float_as_uint(Ks[(k + tig + 4) * KST + sc]);
                mma_tf32(sacc[nt], af, bfr);
            }
        }
        __syncthreads();   // all warps done reading Ks

        // --- issue K(it+1): overlaps softmax + V-wait + PV
        if (it < 7) {
            #pragma unroll
            for (int i = 0; i < 8; i++) {
                int c = lc + i * 8;
                CP_ASYNC16(sK + (uint32_t)(c * KST + lcol) * 4,
                           kp + (size_t)c * NL + s0 + 128 + lcol);
            }
            CP_COMMIT();
        }

        // --- online softmax (row state in registers)
        float mx0 = -1e30f, mx1 = -1e30f;
        #pragma unroll
        for (int nt = 0; nt < 16; nt++) {
            mx0 = fmaxf(mx0, fmaxf(sacc[nt][0], sacc[nt][1]));
            mx1 = fmaxf(mx1, fmaxf(sacc[nt][2], sacc[nt][3]));
        }
        mx0 = fmaxf(mx0, __shfl_xor_sync(0xffffffffu, mx0, 1));
        mx0 = fmaxf(mx0, __shfl_xor_sync(0xffffffffu, mx0, 2));
        mx1 = fmaxf(mx1, __shfl_xor_sync(0xffffffffu, mx1, 1));
        mx1 = fmaxf(mx1, __shfl_xor_sync(0xffffffffu, mx1, 2));
        float mn0 = fmaxf(m0, mx0), mn1 = fmaxf(m1, mx1);
        float sum0 = 0.f, sum1 = 0.f;
        #pragma unroll
        for (int nt = 0; nt < 16; nt++) {
            float p0 = fexp(sacc[nt][0] - mn0);
            float p1 = fexp(sacc[nt][1] - mn0);
            float p2 = fexp(sacc[nt][2] - mn1);
            float p3 = fexp(sacc[nt][3] - mn1);
            sum0 += p0 + p1; sum1 += p2 + p3;
            sacc[nt][0] = p0; sacc[nt][1] = p1;
            sacc[nt][2] = p2; sacc[nt][3] = p3;
        }
        sum0 += __shfl_xor_sync(0xffffffffu, sum0, 1);
        sum0 += __shfl_xor_sync(0xffffffffu, sum0, 2);
        sum1 += __shfl_xor_sync(0xffffffffu, sum1, 1);
        sum1 += __shfl_xor_sync(0xffffffffu, sum1, 2);
        float al0 = fexp(m0 - mn0), al1 = fexp(m1 - mn1);
        l0 = l0 * al0 + sum0;  m0 = mn0;
        l1 = l1 * al1 + sum1;  m1 = mn1;

        // --- wait V(it)  (outstanding: K(it+1) only, except last tile)
        if (it < 7) { CP_WAIT(1); } else { CP_WAIT(0); }
        __syncthreads();

        // --- O = O*alpha + P V^T, P from sacc via shuffles
        #pragma unroll
        for (int nt = 0; nt < 8; nt++) {
            oacc[nt][0] *= al0; oacc[nt][1] *= al0;
            oacc[nt][2] *= al1; oacc[nt][3] *= al1;
        }
        #pragma unroll
        for (int ks = 0; ks < 16; ks++) {
            float x0 = __shfl_sync(0xffffffffu, sacc[ks][0], Lsrc);
            float x1 = __shfl_sync(0xffffffffu, sacc[ks][1], Lsrc);
            float y0 = __shfl_sync(0xffffffffu, sacc[ks][2], Lsrc);
            float y1 = __shfl_sync(0xffffffffu, sacc[ks][3], Lsrc);
            float z0 = __shfl_sync(0xffffffffu, sacc[ks][0], Lsrc + 2);
            float z1 = __shfl_sync(0xffffffffu, sacc[ks][1], Lsrc + 2);
            float w0 = __shfl_sync(0xffffffffu, sacc[ks][2], Lsrc + 2);
            float w1 = __shfl_sync(0xffffffffu, sacc[ks][3], Lsrc + 2);
            uint32_t af[4];
            af[0] = cvt_tf32(hi ? x1 : x0);
            af[1] = cvt_tf32(hi ? y1 : y0);
            af[2] = cvt_tf32(hi ? z1 : z0);
            af[3] = cvt_tf32(hi ? w1 : w0);
            const int k = ks << 3;
            #pragma unroll
            for (int nt = 0; nt < 8; nt++) {
                int cc = (nt << 3) + gid;
                uint32_t bfr[2];
                bfr[0] = __float_as_uint(Vs[cc * VST + k + tig]);
                bfr[1] = __float_as_uint(Vs[cc * VST + k + tig + 4]);
                mma_tf32(oacc[nt], af, bfr);
            }
        }
        __syncthreads();   // all warps done reading Vs

        // --- issue V(it+1): overlaps next tile's QK + softmax
        if (it < 7) {
            #pragma unroll
            for (int i = 0; i < 8; i++) {
                int c = lc + i * 8;
                CP_ASYNC16(sV + (uint32_t)(c * VST + lcol) * 4,
                           vp + (size_t)c * NL + s0 + 128 + lcol);
            }
            CP_COMMIT();
        }
    }

    // epilogue: divide by l, write TRANSPOSED tf32 a_t[b][t0+t][hh*64 + c]
    float inv0 = 1.0f / l0, inv1 = 1.0f / l1;
    float* op = g_at + ((size_t)bi * NL + t0) * NC + hh * 64;
    #pragma unroll
    for (int nt = 0; nt < 8; nt++) {
        int c0 = (nt << 3) + (tig << 1);
        float2 o0, o1;
        o0.x = cvt_tf32f(oacc[nt][0] * inv0); o0.y = cvt_tf32f(oacc[nt][1] * inv0);
        o1.x = cvt_tf32f(oacc[nt][2] * inv1); o1.y = cvt_tf32f(oacc[nt][3] * inv1);
        *(float2*)&op[(size_t)r0 * NC + c0] = o0;
        *(float2*)&op[(size_t)r1 * NC + c0] = o1;
    }
}

// ---------------------------------------------------------------------------
extern "C" void kernel_launch(void* const* d_in, const int* in_sizes, int n_in,
                              void* d_out, int out_size) {
    const float* x     = (const float*)d_in[0];
    const float* nw    = (const float*)d_in[1];
    const float* nb    = (const float*)d_in[2];
    const float* wqkv  = (const float*)d_in[3];
    const float* bqkv  = (const float*)d_in[4];
    const float* wproj = (const float*)d_in[5];
    const float* bproj = (const float*)d_in[6];
    float* out = (float*)d_out;

    float *pht, *pq, *pat, *pwt, *pbq;
    cudaGetSymbolAddress((void**)&pht, g_ht);
    cudaGetSymbolAddress((void**)&pq,  g_qkv);
    cudaGetSymbolAddress((void**)&pat, g_at);
    cudaGetSymbolAddress((void**)&pwt, g_wt);
    cudaGetSymbolAddress((void**)&pbq, g_bq);

    cvt_w_kernel<<<768, 256>>>(wqkv,  pwt,                    NO3 * NC / 4, 1);
    cvt_w_kernel<<<256, 256>>>(wproj, pwt + (size_t)NO3 * NC, NC * NC / 4, 0);
    bias_q_kernel<<<6, 256>>>(bqkv);
    gn_kernel<<<512, 256>>>(x, nw, nb);

    cudaFuncSetAttribute(tc_gemm,
                         cudaFuncAttributeMaxDynamicSharedMemorySize, GEMM_SMEM);
    tc_gemm<<<dim3(8, 12, 16), 256, GEMM_SMEM>>>(pwt, pbq, pht, pq, NO3, 1);

    cudaFuncSetAttribute(attn_kernel,
                         cudaFuncAttributeMaxDynamicSharedMemorySize, ATTN_SMEM);
    attn_kernel<<<dim3(8, 128), 256, ATTN_SMEM>>>();

    tc_gemm<<<dim3(8, 4, 16), 256, GEMM_SMEM>>>(pwt + (size_t)NO3 * NC, bproj,
                                                pat, out, NC, 0);
}

// round 14
// speedup vs baseline: 1.2703x; 1.2703x over previous
#include <cuda_runtime.h>
#include <cstdint>
#include <math.h>

// Problem constants: B=16, C=512, L=1024 (32x32), 32 groups, 8 heads, ch=64.
#define NB   16
#define NC   512
#define NL   1024
#define NO3  1536

// Scratch (device globals; no allocation allowed)
__device__ float g_ht [(size_t)NB * NL * NC];    // groupnorm out, [b][l][c], tf32 bits
__device__ float g_qkv[(size_t)NB * NO3 * NL];   // [b][o][l], tf32 bits (Q pre-scaled)
__device__ float g_at [(size_t)NB * NL * NC];    // attention out, [b][l][c], tf32 bits
__device__ float g_wt [(size_t)(NO3 + NC) * NC]; // weights, tf32 bits (Q rows pre-scaled)
__device__ float g_bq [NO3];                     // qkv bias, Q rows pre-scaled

// ===========================================================================
// helpers
// ===========================================================================
__device__ __forceinline__ uint32_t cvt_tf32(float x) {
    uint32_t r;
    asm("cvt.rna.tf32.f32 %0, %1;" : "=r"(r) : "f"(x));
    return r;
}
__device__ __forceinline__ float cvt_tf32f(float x) {
    return __uint_as_float(cvt_tf32(x));
}
__device__ __forceinline__ void mma_tf32(float* d, const uint32_t* a,
                                         const uint32_t* b) {
    asm volatile(
        "mma.sync.aligned.m16n8k8.row.col.f32.tf32.tf32.f32 "
        "{%0,%1,%2,%3}, {%4,%5,%6,%7}, {%8,%9}, {%0,%1,%2,%3};"
        : "+f"(d[0]), "+f"(d[1]), "+f"(d[2]), "+f"(d[3])
        : "r"(a[0]), "r"(a[1]), "r"(a[2]), "r"(a[3]), "r"(b[0]), "r"(b[1]));
}
#define CP_ASYNC16(dst, src) \
    asm volatile("cp.async.cg.shared.global [%0], [%1], 16;" \
                 :: "r"(dst), "l"(src) : "memory")
#define CP_COMMIT() asm volatile("cp.async.commit_group;" ::: "memory")
#define CP_WAIT(n)  asm volatile("cp.async.wait_group %0;" :: "n"(n) : "memory")

__device__ __forceinline__ uint32_t smem_u32(const void* p) {
    uint32_t a;
    asm("{ .reg .u64 t; cvta.to.shared.u64 t, %1; cvt.u32.u64 %0, t; }"
        : "=r"(a) : "l"(p));
    return a;
}

// fast exp on FMA pipe. x <= 0 expected.
__device__ __forceinline__ float fexp(float x) {
    float y = x * 1.4426950408889634f;
    y = fmaxf(y, -125.0f);
    int   e = __float2int_rd(y);
    float f = y - (float)e;
    float p = fmaf(0.0013333558f, f, 0.0096181291f);
    p = fmaf(p, f, 0.0555041087f);
    p = fmaf(p, f, 0.2402264758f);
    p = fmaf(p, f, 0.6931471806f);
    p = fmaf(p, f, 1.0f);
    return p * __int_as_float((e + 127) << 23);
}

// ---------------------------------------------------------------------------
// Pre-round weights to tf32 bits; optionally scale Q rows (row%192 < 64)
// by 0.125 (softmax scale folded into the QKV projection).
// ---------------------------------------------------------------------------
__global__ __launch_bounds__(256) void cvt_w_kernel(const float* __restrict__ src,
                                                    float* __restrict__ dst,
                                                    int n4, int qmode) {
    int i = blockIdx.x * 256 + threadIdx.x;
    if (i < n4) {
        float s = 1.0f;
        if (qmode) {
            int row = i >> 7;                 // NC/4 = 128 float4 per row
            s = ((row % 192) < 64) ? 0.125f : 1.0f;
        }
        float4 v = ((const float4*)src)[i];
        v.x = cvt_tf32f(v.x * s); v.y = cvt_tf32f(v.y * s);
        v.z = cvt_tf32f(v.z * s); v.w = cvt_tf32f(v.w * s);
        ((float4*)dst)[i] = v;
    }
}

__global__ __launch_bounds__(256) void bias_q_kernel(const float* __restrict__ b) {
    int i = blockIdx.x * 256 + threadIdx.x;
    if (i < NO3) g_bq[i] = b[i] * (((i % 192) < 64) ? 0.125f : 1.0f);
}

// ---------------------------------------------------------------------------
// GroupNorm: one block per (batch, group); writes TRANSPOSED h_t[b][l][c],
// tf32-rounded bits. Sector-efficient both ways (R11 version, confirmed win).
// ---------------------------------------------------------------------------
__global__ __launch_bounds__(256) void gn_kernel(const float* __restrict__ x,
                                                 const float* __restrict__ w,
                                                 const float* __restrict__ b) {
    const int blk = blockIdx.x;
    const int bi  = blk >> 5;
    const int g   = blk & 31;
    const int cb  = g << 4;
    const float* xg = x + ((size_t)bi * NC + (size_t)cb) * NL;
    const int tid = threadIdx.x;

    float s = 0.f, s2 = 0.f;
    for (int v = tid; v < 4096; v += 256) {
        float4 q = *(const float4*)(xg + (size_t)v * 4);
        s  += q.x + q.y + q.z + q.w;
        s2 += q.x*q.x + q.y*q.y + q.z*q.z + q.w*q.w;
    }
    #pragma unroll
    for (int d = 16; d; d >>= 1) {
        s  += __shfl_xor_sync(0xffffffffu, s,  d);
        s2 += __shfl_xor_sync(0xffffffffu, s2, d);
    }
    __shared__ float rs[8], rs2[8];
    __shared__ float smean, srstd;
    if ((tid & 31) == 0) { rs[tid >> 5] = s; rs2[tid >> 5] = s2; }
    __syncthreads();
    if (tid == 0) {
        float ts = 0.f, ts2 = 0.f;
        #pragma unroll
        for (int i = 0; i < 8; i++) { ts += rs[i]; ts2 += rs2[i]; }
        float mean = ts * (1.0f / 16384.0f);
        float var  = ts2 * (1.0f / 16384.0f) - mean * mean;
        smean = mean;
        srstd = rsqrtf(var + 1e-5f);
    }
    __syncthreads();
    const float mean = smean, rstd = srstd;

    const int cq = (tid & 3) << 2;
    const int lb = tid >> 2;
    float wc[4], bc[4];
    const float* xr[4];
    #pragma unroll
    for (int i = 0; i < 4; i++) {
        wc[i] = w[cb + cq + i] * rstd;
        bc[i] = b[cb + cq + i];
        xr[i] = x + ((size_t)bi * NC + cb + cq + i) * NL;
    }
    float* ob = g_ht + (size_t)bi * NL * NC + cb + cq;
    #pragma unroll
    for (int it = 0; it < 16; it++) {
        const int l = lb + (it << 6);
        float4 o;
        o.x = cvt_tf32f((xr[0][l] - mean) * wc[0] + bc[0]);
        o.y = cvt_tf32f((xr[1][l] - mean) * wc[1] + bc[1]);
        o.z = cvt_tf32f((xr[2][l] - mean) * wc[2] + bc[2]);
        o.w = cvt_tf32f((xr[3][l] - mean) * wc[3] + bc[3]);
        *(float4*)&ob[(size_t)l * NC] = o;
    }
}

// ---------------------------------------------------------------------------
// mma.sync tf32 GEMM + bias. AST=32 with XOR swizzle: word column
// col' = col ^ ((row&7)<<2). cp.async stores keep optimal phases; all
// fragment LDS become conflict-free (previous AST=40 had a 2-way conflict
// on every fragment load: bank = (8 gid + tig), gid vs gid+4 collide).
// ---------------------------------------------------------------------------
#define AST 32
#define TILE_F (128 * AST)
#define GEMM_SMEM (4 * TILE_F * 4)            // 65536 B

__global__ __launch_bounds__(256, 2) void tc_gemm(const float* __restrict__ W,
                                                  const float* __restrict__ bias,
                                                  const float* __restrict__ Xt,
                                                  float* __restrict__ Y,
                                                  int M, int rnd) {
    extern __shared__ float smf[];
    const int tid  = threadIdx.x;
    const int wid  = tid >> 5;
    const int lane = tid & 31;
    const int gid  = lane >> 2;
    const int tig  = lane & 3;
    const int K    = NC;
    const int n_blk = blockIdx.x << 7;
    const int m_blk = blockIdx.y << 7;
    const float* Xb = Xt + (size_t)blockIdx.z * NL * K;
    float*       Yb = Y  + (size_t)blockIdx.z * M * NL;
    const int wm = (wid >> 1) << 5;
    const int wn = (wid & 1) << 6;

    const int lrow = tid >> 3;                       // 0..31 (+32 per i)
    const int lkg  = (tid & 7) << 2;                 // 0,4,..,28
    const int lkgs = lkg ^ ((lrow & 7) << 2);        // swizzled store column
    const uint32_t sbase = smem_u32(smf);
    const int swz  = gid << 2;                       // fragment swizzle const

    float acc[2][8][4];
    #pragma unroll
    for (int a = 0; a < 2; a++)
        #pragma unroll
        for (int b = 0; b < 8; b++)
            #pragma unroll
            for (int c = 0; c < 4; c++) acc[a][b][c] = 0.f;

    const int nkt = K / 32;
    {
        const float* wp = W  + (size_t)(m_blk + lrow) * K + lkg;
        const float* xp = Xb + (size_t)(n_blk + lrow) * K + lkg;
        #pragma unroll
        for (int i = 0; i < 4; i++) {
            uint32_t da = sbase + ((lrow + i * 32) * AST + lkgs) * 4;
            uint32_t db = da + TILE_F * 4;
            CP_ASYNC16(da, wp + (size_t)i * 32 * K);
            CP_ASYNC16(db, xp + (size_t)i * 32 * K);
        }
        CP_COMMIT();
    }

    for (int kt = 0; kt < nkt; kt++) {
        const int bf = kt & 1;
        if (kt + 1 < nkt) {
            const int k0 = (kt + 1) << 5;
            const float* wp = W  + (size_t)(m_blk + lrow) * K + k0 + lkg;
            const float* xp = Xb + (size_t)(n_blk + lrow) * K + k0 + lkg;
            uint32_t base = sbase + (((kt + 1) & 1) ? 2 * TILE_F * 4 : 0);
            #pragma unroll
            for (int i = 0; i < 4; i++) {
                uint32_t da = base + ((lrow + i * 32) * AST + lkgs) * 4;
                uint32_t db = da + TILE_F * 4;
                CP_ASYNC16(da, wp + (size_t)i * 32 * K);
                CP_ASYNC16(db, xp + (size_t)i * 32 * K);
            }
            CP_COMMIT();
            CP_WAIT(1);
        } else {
            CP_WAIT(0);
        }
        __syncthreads();

        const float* As = smf + (bf ? 2 * TILE_F : 0);
        const float* Bs = As + TILE_F;
        #pragma unroll
        for (int ks = 0; ks < 4; ks++) {
            const int k  = ks << 3;
            const int c0 = (k + tig) ^ swz;          // swizzled frag columns
            const int c4 = (k + tig + 4) ^ swz;
            uint32_t af[2][4];
            #pragma unroll
            for (int mt = 0; mt < 2; mt++) {
                int r0 = wm + (mt << 4) + gid;
                af[mt][0] = __float_as_uint(As[r0 * AST + c0]);
                af[mt][1] = __float_as_uint(As[(r0 + 8) * AST + c0]);
                af[mt][2] = __float_as_uint(As[r0 * AST + c4]);
                af[mt][3] = __float_as_uint(As[(r0 + 8) * AST + c4]);
            }
            #pragma unroll
            for (int nt = 0; nt < 8; nt++) {
                int n0 = wn + (nt << 3) + gid;
                uint32_t bfr[2];
                bfr[0] = __float_as_uint(Bs[n0 * AST + c0]);
                bfr[1] = __float_as_uint(Bs[n0 * AST + c4]);
                mma_tf32(acc[0][nt], af[0], bfr);
                mma_tf32(acc[1][nt], af[1], bfr);
            }
        }
        __syncthreads();
    }

    #pragma unroll
    for (int mt = 0; mt < 2; mt++) {
        int m = m_blk + wm + (mt << 4) + gid;
        float bv0 = bias[m], bv1 = bias[m + 8];
        #pragma unroll
        for (int nt = 0; nt < 8; nt++) {
            int n = n_blk + wn + (nt << 3) + (tig << 1);
            float2 o0, o1;
            if (rnd) {
                o0.x = cvt_tf32f(acc[mt][nt][0] + bv0);
                o0.y = cvt_tf32f(acc[mt][nt][1] + bv0);
                o1.x = cvt_tf32f(acc[mt][nt][2] + bv1);
                o1.y = cvt_tf32f(acc[mt][nt][3] + bv1);
            } else {
                o0.x = acc[mt][nt][0] + bv0; o0.y = acc[mt][nt][1] + bv0;
                o1.x = acc[mt][nt][2] + bv1; o1.y = acc[mt][nt][3] + bv1;
            }
            *(float2*)&Yb[(size_t)m * NL + n]       = o0;
            *(float2*)&Yb[(size_t)(m + 8) * NL + n] = o1;
        }
    }
}

// ---------------------------------------------------------------------------
// Flash attention, mma.sync tf32, register-P, fully async K/V pipeline.
// K stride back to 136 (R11's 132 was a mis-derived "fix": the B-fragment
// pattern Ks[(k+tig)*KST + 8nt+gid] has bank (KST*tig+gid); 136 -> 8tig+gid
// = conflict-free, 132 -> 4tig+gid = 2-way conflicted).
// smem = Q(64x136) + K(64x136) + V(64x132) = 103,424 B  ->  2 CTAs/SM.
// ---------------------------------------------------------------------------
#define QST 136
#define KST 136
#define VST 132
#define ATTN_SMEM ((64 * QST + 64 * KST + 64 * VST) * 4)

__global__ __launch_bounds__(256, 2) void attn_kernel() {
    extern __shared__ float sm[];
    float* Qs = sm;                     // 64 x 136  [c][t]
    float* Ks = Qs + 64 * QST;          // 64 x 136  [c][s]
    float* Vs = Ks + 64 * KST;          // 64 x 132  [c][s]

    const int head = blockIdx.y;
    const int bi = head >> 3, hh = head & 7;
    const int t0 = blockIdx.x << 7;
    const float* qp = g_qkv + ((size_t)bi * NO3 + (size_t)hh * 192) * NL;
    const float* kp = qp + (size_t)64 * NL;
    const float* vp = kp + (size_t)64 * NL;
    const int tid  = threadIdx.x;
    const int wid  = tid >> 5;
    const int lane = tid & 31;
    const int gid  = lane >> 2;
    const int tig  = lane & 3;
    const int tb   = wid << 4;
    const int r0   = tb + gid, r1 = r0 + 8;

    const int lc   = tid >> 5;
    const int lcol = (tid & 31) << 2;

    const int Lsrc = (lane & 0x1c) | (tig >> 1);
    const bool hi  = (tig & 1);

    const uint32_t sQ = smem_u32(Qs);
    const uint32_t sK = smem_u32(Ks);
    const uint32_t sV = smem_u32(Vs);

    // async prologue: G0 = Q + K0, G1 = V0
    #pragma unroll
    for (int i = 0; i < 8; i++) {
        int c = lc + i * 8;
        CP_ASYNC16(sQ + (uint32_t)(c * QST + lcol) * 4,
                   qp + (size_t)c * NL + t0 + lcol);
        CP_ASYNC16(sK + (uint32_t)(c * KST + lcol) * 4,
                   kp + (size_t)c * NL + lcol);
    }
    CP_COMMIT();
    #pragma unroll
    for (int i = 0; i < 8; i++) {
        int c = lc + i * 8;
        CP_ASYNC16(sV + (uint32_t)(c * VST + lcol) * 4,
                   vp + (size_t)c * NL + lcol);
    }
    CP_COMMIT();

    float m0 = -1e30f, m1 = -1e30f, l0 = 0.f, l1 = 0.f;
    float oacc[8][4];
    #pragma unroll
    for (int i = 0; i < 8; i++)
        #pragma unroll
        for (int j = 0; j < 4; j++) oacc[i][j] = 0.f;

    for (int it = 0; it < 8; it++) {
        const int s0 = it << 7;
        CP_WAIT(1);
        __syncthreads();

        // --- S = Q^T K
        float sacc[16][4];
        #pragma unroll
        for (int i = 0; i < 16; i++)
            #pragma unroll
            for (int j = 0; j < 4; j++) sacc[i][j] = 0.f;
        #pragma unroll
        for (int ks = 0; ks < 8; ks++) {
            const int k = ks << 3;
            uint32_t af[4];
            af[0] = __float_as_uint(Qs[(k + tig) * QST + tb + gid]);
            af[1] = __float_as_uint(Qs[(k + tig) * QST + tb + gid + 8]);
            af[2] = __float_as_uint(Qs[(k + tig + 4) * QST + tb + gid]);
            af[3] = __float_as_uint(Qs[(k + tig + 4) * QST + tb + gid + 8]);
            #pragma unroll
            for (int nt = 0; nt < 16; nt++) {
                int sc = (nt << 3) + gid;
                uint32_t bfr[2];
                bfr[0] = __float_as_uint(Ks[(k + tig) * KST + sc]);
                bfr[1] = __float_as_uint(Ks[(k + tig + 4) * KST + sc]);
                mma_tf32(sacc[nt], af, bfr);
            }
        }
        __syncthreads();

        // --- issue K(it+1)
        if (it < 7) {
            #pragma unroll
            for (int i = 0; i < 8; i++) {
                int c = lc + i * 8;
                CP_ASYNC16(sK + (uint32_t)(c * KST + lcol) * 4,
                           kp + (size_t)c * NL + s0 + 128 + lcol);
            }
            CP_COMMIT();
        }

        // --- online softmax (row state in registers)
        float mx0 = -1e30f, mx1 = -1e30f;
        #pragma unroll
        for (int nt = 0; nt < 16; nt++) {
            mx0 = fmaxf(mx0, fmaxf(sacc[nt][0], sacc[nt][1]));
            mx1 = fmaxf(mx1, fmaxf(sacc[nt][2], sacc[nt][3]));
        }
        mx0 = fmaxf(mx0, __shfl_xor_sync(0xffffffffu, mx0, 1));
        mx0 = fmaxf(mx0, __shfl_xor_sync(0xffffffffu, mx0, 2));
        mx1 = fmaxf(mx1, __shfl_xor_sync(0xffffffffu, mx1, 1));
        mx1 = fmaxf(mx1, __shfl_xor_sync(0xffffffffu, mx1, 2));
        float mn0 = fmaxf(m0, mx0), mn1 = fmaxf(m1, mx1);
        float sum0 = 0.f, sum1 = 0.f;
        #pragma unroll
        for (int nt = 0; nt < 16; nt++) {
            float p0 = fexp(sacc[nt][0] - mn0);
            float p1 = fexp(sacc[nt][1] - mn0);
            float p2 = fexp(sacc[nt][2] - mn1);
            float p3 = fexp(sacc[nt][3] - mn1);
            sum0 += p0 + p1; sum1 += p2 + p3;
            sacc[nt][0] = p0; sacc[nt][1] = p1;
            sacc[nt][2] = p2; sacc[nt][3] = p3;
        }
        sum0 += __shfl_xor_sync(0xffffffffu, sum0, 1);
        sum0 += __shfl_xor_sync(0xffffffffu, sum0, 2);
        sum1 += __shfl_xor_sync(0xffffffffu, sum1, 1);
        sum1 += __shfl_xor_sync(0xffffffffu, sum1, 2);
        float al0 = fexp(m0 - mn0), al1 = fexp(m1 - mn1);
        l0 = l0 * al0 + sum0;  m0 = mn0;
        l1 = l1 * al1 + sum1;  m1 = mn1;

        // --- wait V(it)
        if (it < 7) { CP_WAIT(1); } else { CP_WAIT(0); }
        __syncthreads();

        // --- O = O*alpha + P V^T, P from sacc via shuffles
        #pragma unroll
        for (int nt = 0; nt < 8; nt++) {
            oacc[nt][0] *= al0; oacc[nt][1] *= al0;
            oacc[nt][2] *= al1; oacc[nt][3] *= al1;
        }
        #pragma unroll
        for (int ks = 0; ks < 16; ks++) {
            float x0 = __shfl_sync(0xffffffffu, sacc[ks][0], Lsrc);
            float x1 = __shfl_sync(0xffffffffu, sacc[ks][1], Lsrc);
            float y0 = __shfl_sync(0xffffffffu, sacc[ks][2], Lsrc);
            float y1 = __shfl_sync(0xffffffffu, sacc[ks][3], Lsrc);
            float z0 = __shfl_sync(0xffffffffu, sacc[ks][0], Lsrc + 2);
            float z1 = __shfl_sync(0xffffffffu, sacc[ks][1], Lsrc + 2);
            float w0 = __shfl_sync(0xffffffffu, sacc[ks][2], Lsrc + 2);
            float w1 = __shfl_sync(0xffffffffu, sacc[ks][3], Lsrc + 2);
            uint32_t af[4];
            af[0] = cvt_tf32(hi ? x1 : x0);
            af[1] = cvt_tf32(hi ? y1 : y0);
            af[2] = cvt_tf32(hi ? z1 : z0);
            af[3] = cvt_tf32(hi ? w1 : w0);
            const int k = ks << 3;
            #pragma unroll
            for (int nt = 0; nt < 8; nt++) {
                int cc = (nt << 3) + gid;
                uint32_t bfr[2];
                bfr[0] = __float_as_uint(Vs[cc * VST + k + tig]);
                bfr[1] = __float_as_uint(Vs[cc * VST + k + tig + 4]);
                mma_tf32(oacc[nt], af, bfr);
            }
        }
        __syncthreads();

        // --- issue V(it+1)
        if (it < 7) {
            #pragma unroll
            for (int i = 0; i < 8; i++) {
                int c = lc + i * 8;
                CP_ASYNC16(sV + (uint32_t)(c * VST + lcol) * 4,
                           vp + (size_t)c * NL + s0 + 128 + lcol);
            }
            CP_COMMIT();
        }
    }

    // epilogue: divide by l, write TRANSPOSED tf32 a_t[b][t0+t][hh*64 + c]
    float inv0 = 1.0f / l0, inv1 = 1.0f / l1;
    float* op = g_at + ((size_t)bi * NL + t0) * NC + hh * 64;
    #pragma unroll
    for (int nt = 0; nt < 8; nt++) {
        int c0 = (nt << 3) + (tig << 1);
        float2 o0, o1;
        o0.x = cvt_tf32f(oacc[nt][0] * inv0); o0.y = cvt_tf32f(oacc[nt][1] * inv0);
        o1.x = cvt_tf32f(oacc[nt][2] * inv1); o1.y = cvt_tf32f(oacc[nt][3] * inv1);
        *(float2*)&op[(size_t)r0 * NC + c0] = o0;
        *(float2*)&op[(size_t)r1 * NC + c0] = o1;
    }
}

// ---------------------------------------------------------------------------
extern "C" void kernel_launch(void* const* d_in, const int* in_sizes, int n_in,
                              void* d_out, int out_size) {
    const float* x     = (const float*)d_in[0];
    const float* nw    = (const float*)d_in[1];
    const float* nb    = (const float*)d_in[2];
    const float* wqkv  = (const float*)d_in[3];
    const float* bqkv  = (const float*)d_in[4];
    const float* wproj = (const float*)d_in[5];
    const float* bproj = (const float*)d_in[6];
    float* out = (float*)d_out;

    float *pht, *pq, *pat, *pwt, *pbq;
    cudaGetSymbolAddress((void**)&pht, g_ht);
    cudaGetSymbolAddress((void**)&pq,  g_qkv);
    cudaGetSymbolAddress((void**)&pat, g_at);
    cudaGetSymbolAddress((void**)&pwt, g_wt);
    cudaGetSymbolAddress((void**)&pbq, g_bq);

    cvt_w_kernel<<<768, 256>>>(wqkv,  pwt,                    NO3 * NC / 4, 1);
    cvt_w_kernel<<<256, 256>>>(wproj, pwt + (size_t)NO3 * NC, NC * NC / 4, 0);
    bias_q_kernel<<<6, 256>>>(bqkv);
    gn_kernel<<<512, 256>>>(x, nw, nb);

    cudaFuncSetAttribute(tc_gemm,
                         cudaFuncAttributeMaxDynamicSharedMemorySize, GEMM_SMEM);
    tc_gemm<<<dim3(8, 12, 16), 256, GEMM_SMEM>>>(pwt, pbq, pht, pq, NO3, 1);

    cudaFuncSetAttribute(attn_kernel,
                         cudaFuncAttributeMaxDynamicSharedMemorySize, ATTN_SMEM);
    attn_kernel<<<dim3(8, 128), 256, ATTN_SMEM>>>();

    tc_gemm<<<dim3(8, 4, 16), 256, GEMM_SMEM>>>(pwt + (size_t)NO3 * NC, bproj,
                                                pat, out, NC, 0);
}

// round 15
// speedup vs baseline: 1.2754x; 1.0040x over previous
#include <cuda_runtime.h>
#include <cuda_fp16.h>
#include <cstdint>
#include <math.h>

// Problem constants: B=16, C=512, L=1024 (32x32), 32 groups, 8 heads, ch=64.
#define NB   16
#define NC   512
#define NL   1024
#define NO3  1536

// Scratch (device globals; no allocation allowed)
__device__ float  g_ht [(size_t)NB * NL * NC];    // groupnorm out, [b][l][c], tf32 bits
__device__ float  g_qkv[(size_t)NB * NO3 * NL];   // [b][o][l], tf32 bits (Q pre-scaled)
__device__ float  g_at [(size_t)NB * NL * NC];    // attention out, [b][l][c], tf32 bits
__device__ float  g_wt [(size_t)(NO3 + NC) * NC]; // weights, tf32 bits (Q rows pre-scaled)
__device__ float  g_bq [NO3];                     // qkv bias, Q rows pre-scaled
__device__ __half g_qh [(size_t)128 * NL * 64];   // Q fp16, [head][l][c]
__device__ __half g_kh [(size_t)128 * NL * 64];   // K fp16, [head][s][c]
__device__ __half g_vh [(size_t)128 * 64 * NL];   // V fp16, [head][c][s]

// ===========================================================================
// helpers
// ===========================================================================
__device__ __forceinline__ uint32_t cvt_tf32(float x) {
    uint32_t r;
    asm("cvt.rna.tf32.f32 %0, %1;" : "=r"(r) : "f"(x));
    return r;
}
__device__ __forceinline__ float cvt_tf32f(float x) {
    return __uint_as_float(cvt_tf32(x));
}
__device__ __forceinline__ void mma_tf32(float* d, const uint32_t* a,
                                         const uint32_t* b) {
    asm volatile(
        "mma.sync.aligned.m16n8k8.row.col.f32.tf32.tf32.f32 "
        "{%0,%1,%2,%3}, {%4,%5,%6,%7}, {%8,%9}, {%0,%1,%2,%3};"
        : "+f"(d[0]), "+f"(d[1]), "+f"(d[2]), "+f"(d[3])
        : "r"(a[0]), "r"(a[1]), "r"(a[2]), "r"(a[3]), "r"(b[0]), "r"(b[1]));
}
__device__ __forceinline__ void mma_f16(float* d, const uint32_t* a,
                                        const uint32_t* b) {
    asm volatile(
        "mma.sync.aligned.m16n8k16.row.col.f32.f16.f16.f32 "
        "{%0,%1,%2,%3}, {%4,%5,%6,%7}, {%8,%9}, {%0,%1,%2,%3};"
        : "+f"(d[0]), "+f"(d[1]), "+f"(d[2]), "+f"(d[3])
        : "r"(a[0]), "r"(a[1]), "r"(a[2]), "r"(a[3]), "r"(b[0]), "r"(b[1]));
}
__device__ __forceinline__ uint32_t pack_h2(float lo, float hi) {
    uint32_t d;
    asm("cvt.rn.f16x2.f32 %0, %1, %2;" : "=r"(d) : "f"(hi), "f"(lo));
    return d;
}
#define CP_ASYNC16(dst, src) \
    asm volatile("cp.async.cg.shared.global [%0], [%1], 16;" \
                 :: "r"(dst), "l"(src) : "memory")
#define CP_COMMIT() asm volatile("cp.async.commit_group;" ::: "memory")
#define CP_WAIT(n)  asm volatile("cp.async.wait_group %0;" :: "n"(n) : "memory")

__device__ __forceinline__ uint32_t smem_u32(const void* p) {
    uint32_t a;
    asm("{ .reg .u64 t; cvta.to.shared.u64 t, %1; cvt.u32.u64 %0, t; }"
        : "=r"(a) : "l"(p));
    return a;
}

// fast exp on FMA pipe. x <= 0 expected.
__device__ __forceinline__ float fexp(float x) {
    float y = x * 1.4426950408889634f;
    y = fmaxf(y, -125.0f);
    int   e = __float2int_rd(y);
    float f = y - (float)e;
    float p = fmaf(0.0013333558f, f, 0.0096181291f);
    p = fmaf(p, f, 0.0555041087f);
    p = fmaf(p, f, 0.2402264758f);
    p = fmaf(p, f, 0.6931471806f);
    p = fmaf(p, f, 1.0f);
    return p * __int_as_float((e + 127) << 23);
}

// ---------------------------------------------------------------------------
// Pre-round weights to tf32 bits; optionally scale Q rows by 0.125.
// ---------------------------------------------------------------------------
__global__ __launch_bounds__(256) void cvt_w_kernel(const float* __restrict__ src,
                                                    float* __restrict__ dst,
                                                    int n4, int qmode) {
    int i = blockIdx.x * 256 + threadIdx.x;
    if (i < n4) {
        float s = 1.0f;
        if (qmode) {
            int row = i >> 7;
            s = ((row % 192) < 64) ? 0.125f : 1.0f;
        }
        float4 v = ((const float4*)src)[i];
        v.x = cvt_tf32f(v.x * s); v.y = cvt_tf32f(v.y * s);
        v.z = cvt_tf32f(v.z * s); v.w = cvt_tf32f(v.w * s);
        ((float4*)dst)[i] = v;
    }
}

__global__ __launch_bounds__(256) void bias_q_kernel(const float* __restrict__ b) {
    int i = blockIdx.x * 256 + threadIdx.x;
    if (i < NO3) g_bq[i] = b[i] * (((i % 192) < 64) ? 0.125f : 1.0f);
}

// ---------------------------------------------------------------------------
// GroupNorm (R11 coalesced version, confirmed).
// ---------------------------------------------------------------------------
__global__ __launch_bounds__(256) void gn_kernel(const float* __restrict__ x,
                                                 const float* __restrict__ w,
                                                 const float* __restrict__ b) {
    const int blk = blockIdx.x;
    const int bi  = blk >> 5;
    const int g   = blk & 31;
    const int cb  = g << 4;
    const float* xg = x + ((size_t)bi * NC + (size_t)cb) * NL;
    const int tid = threadIdx.x;

    float s = 0.f, s2 = 0.f;
    for (int v = tid; v < 4096; v += 256) {
        float4 q = *(const float4*)(xg + (size_t)v * 4);
        s  += q.x + q.y + q.z + q.w;
        s2 += q.x*q.x + q.y*q.y + q.z*q.z + q.w*q.w;
    }
    #pragma unroll
    for (int d = 16; d; d >>= 1) {
        s  += __shfl_xor_sync(0xffffffffu, s,  d);
        s2 += __shfl_xor_sync(0xffffffffu, s2, d);
    }
    __shared__ float rs[8], rs2[8];
    __shared__ float smean, srstd;
    if ((tid & 31) == 0) { rs[tid >> 5] = s; rs2[tid >> 5] = s2; }
    __syncthreads();
    if (tid == 0) {
        float ts = 0.f, ts2 = 0.f;
        #pragma unroll
        for (int i = 0; i < 8; i++) { ts += rs[i]; ts2 += rs2[i]; }
        float mean = ts * (1.0f / 16384.0f);
        float var  = ts2 * (1.0f / 16384.0f) - mean * mean;
        smean = mean;
        srstd = rsqrtf(var + 1e-5f);
    }
    __syncthreads();
    const float mean = smean, rstd = srstd;

    const int cq = (tid & 3) << 2;
    const int lb = tid >> 2;
    float wc[4], bc[4];
    const float* xr[4];
    #pragma unroll
    for (int i = 0; i < 4; i++) {
        wc[i] = w[cb + cq + i] * rstd;
        bc[i] = b[cb + cq + i];
        xr[i] = x + ((size_t)bi * NC + cb + cq + i) * NL;
    }
    float* ob = g_ht + (size_t)bi * NL * NC + cb + cq;
    #pragma unroll
    for (int it = 0; it < 16; it++) {
        const int l = lb + (it << 6);
        float4 o;
        o.x = cvt_tf32f((xr[0][l] - mean) * wc[0] + bc[0]);
        o.y = cvt_tf32f((xr[1][l] - mean) * wc[1] + bc[1]);
        o.z = cvt_tf32f((xr[2][l] - mean) * wc[2] + bc[2]);
        o.w = cvt_tf32f((xr[3][l] - mean) * wc[3] + bc[3]);
        *(float4*)&ob[(size_t)l * NC] = o;
    }
}

// ---------------------------------------------------------------------------
// mma.sync tf32 GEMM + bias (R14 version: AST=32 + XOR swizzle, unchanged).
// ---------------------------------------------------------------------------
#define AST 32
#define TILE_F (128 * AST)
#define GEMM_SMEM (4 * TILE_F * 4)            // 65536 B

__global__ __launch_bounds__(256, 2) void tc_gemm(const float* __restrict__ W,
                                                  const float* __restrict__ bias,
                                                  const float* __restrict__ Xt,
                                                  float* __restrict__ Y,
                                                  int M, int rnd) {
    extern __shared__ float smf[];
    const int tid  = threadIdx.x;
    const int wid  = tid >> 5;
    const int lane = tid & 31;
    const int gid  = lane >> 2;
    const int tig  = lane & 3;
    const int K    = NC;
    const int n_blk = blockIdx.x << 7;
    const int m_blk = blockIdx.y << 7;
    const float* Xb = Xt + (size_t)blockIdx.z * NL * K;
    float*       Yb = Y  + (size_t)blockIdx.z * M * NL;
    const int wm = (wid >> 1) << 5;
    const int wn = (wid & 1) << 6;

    const int lrow = tid >> 3;
    const int lkg  = (tid & 7) << 2;
    const int lkgs = lkg ^ ((lrow & 7) << 2);
    const uint32_t sbase = smem_u32(smf);
    const int swz  = gid << 2;

    float acc[2][8][4];
    #pragma unroll
    for (int a = 0; a < 2; a++)
        #pragma unroll
        for (int b = 0; b < 8; b++)
            #pragma unroll
            for (int c = 0; c < 4; c++) acc[a][b][c] = 0.f;

    const int nkt = K / 32;
    {
        const float* wp = W  + (size_t)(m_blk + lrow) * K + lkg;
        const float* xp = Xb + (size_t)(n_blk + lrow) * K + lkg;
        #pragma unroll
        for (int i = 0; i < 4; i++) {
            uint32_t da = sbase + ((lrow + i * 32) * AST + lkgs) * 4;
            uint32_t db = da + TILE_F * 4;
            CP_ASYNC16(da, wp + (size_t)i * 32 * K);
            CP_ASYNC16(db, xp + (size_t)i * 32 * K);
        }
        CP_COMMIT();
    }

    for (int kt = 0; kt < nkt; kt++) {
        const int bf = kt & 1;
        if (kt + 1 < nkt) {
            const int k0 = (kt + 1) << 5;
            const float* wp = W  + (size_t)(m_blk + lrow) * K + k0 + lkg;
            const float* xp = Xb + (size_t)(n_blk + lrow) * K + k0 + lkg;
            uint32_t base = sbase + (((kt + 1) & 1) ? 2 * TILE_F * 4 : 0);
            #pragma unroll
            for (int i = 0; i < 4; i++) {
                uint32_t da = base + ((lrow + i * 32) * AST + lkgs) * 4;
                uint32_t db = da + TILE_F * 4;
                CP_ASYNC16(da, wp + (size_t)i * 32 * K);
                CP_ASYNC16(db, xp + (size_t)i * 32 * K);
            }
            CP_COMMIT();
            CP_WAIT(1);
        } else {
            CP_WAIT(0);
        }
        __syncthreads();

        const float* As = smf + (bf ? 2 * TILE_F : 0);
        const float* Bs = As + TILE_F;
        #pragma unroll
        for (int ks = 0; ks < 4; ks++) {
            const int k  = ks << 3;
            const int c0 = (k + tig) ^ swz;
            const int c4 = (k + tig + 4) ^ swz;
            uint32_t af[2][4];
            #pragma unroll
            for (int mt = 0; mt < 2; mt++) {
                int r0 = wm + (mt << 4) + gid;
                af[mt][0] = __float_as_uint(As[r0 * AST + c0]);
                af[mt][1] = __float_as_uint(As[(r0 + 8) * AST + c0]);
                af[mt][2] = __float_as_uint(As[r0 * AST + c4]);
                af[mt][3] = __float_as_uint(As[(r0 + 8) * AST + c4]);
            }
            #pragma unroll
            for (int nt = 0; nt < 8; nt++) {
                int n0 = wn + (nt << 3) + gid;
                uint32_t bfr[2];
                bfr[0] = __float_as_uint(Bs[n0 * AST + c0]);
                bfr[1] = __float_as_uint(Bs[n0 * AST + c4]);
                mma_tf32(acc[0][nt], af[0], bfr);
                mma_tf32(acc[1][nt], af[1], bfr);
            }
        }
        __syncthreads();
    }

    #pragma unroll
    for (int mt = 0; mt < 2; mt++) {
        int m = m_blk + wm + (mt << 4) + gid;
        float bv0 = bias[m], bv1 = bias[m + 8];
        #pragma unroll
        for (int nt = 0; nt < 8; nt++) {
            int n = n_blk + wn + (nt << 3) + (tig << 1);
            float2 o0, o1;
            if (rnd) {
                o0.x = cvt_tf32f(acc[mt][nt][0] + bv0);
                o0.y = cvt_tf32f(acc[mt][nt][1] + bv0);
                o1.x = cvt_tf32f(acc[mt][nt][2] + bv1);
                o1.y = cvt_tf32f(acc[mt][nt][3] + bv1);
            } else {
                o0.x = acc[mt][nt][0] + bv0; o0.y = acc[mt][nt][1] + bv0;
                o1.x = acc[mt][nt][2] + bv1; o1.y = acc[mt][nt][3] + bv1;
            }
            *(float2*)&Yb[(size_t)m * NL + n]       = o0;
            *(float2*)&Yb[(size_t)(m + 8) * NL + n] = o1;
        }
    }
}

// ---------------------------------------------------------------------------
// Repack Q/K: g_qkv fp32 [c][l] -> fp16 [l][c] per head (transpose via smem).
// grid = (8 l-chunks, 128 heads, 2 {Q,K}), 256 threads.
// ---------------------------------------------------------------------------
__global__ __launch_bounds__(256) void qk_pack() {
    const int l0   = blockIdx.x << 7;
    const int head = blockIdx.y;
    const int z    = blockIdx.z;
    const int bi = head >> 3, hh = head & 7;
    const float* src = g_qkv + ((size_t)bi * NO3 + hh * 192 + (z ? 64 : 0)) * NL;
    __half* dst = (z ? g_kh : g_qh) + (size_t)head * NL * 64;
    __shared__ __half sh[128 * 72];
    const int tid = threadIdx.x;

    #pragma unroll
    for (int i = 0; i < 8; i++) {
        int idx = tid + (i << 8);
        int c   = idx >> 5;
        int jj  = (idx & 31) << 2;
        float4 v = *(const float4*)&src[(size_t)c * NL + l0 + jj];
        sh[(jj + 0) * 72 + c] = __float2half_rn(v.x);
        sh[(jj + 1) * 72 + c] = __float2half_rn(v.y);
        sh[(jj + 2) * 72 + c] = __float2half_rn(v.z);
        sh[(jj + 3) * 72 + c] = __float2half_rn(v.w);
    }
    __syncthreads();
    #pragma unroll
    for (int i = 0; i < 4; i++) {
        int idx = tid + (i << 8);
        int row = idx >> 3, j = idx & 7;
        uint4 v = *(const uint4*)&sh[row * 72 + j * 8];
        *(uint4*)&dst[((size_t)(l0 + row)) * 64 + j * 8] = v;
    }
}

// ---------------------------------------------------------------------------
// Repack V: g_qkv fp32 [c][l] -> fp16 [c][l] per head (straight cvt copy).
// grid = 128 heads, 256 threads.
// ---------------------------------------------------------------------------
__global__ __launch_bounds__(256) void v_pack() {
    const int head = blockIdx.x;
    const int bi = head >> 3, hh = head & 7;
    const float* src = g_qkv + ((size_t)bi * NO3 + hh * 192 + 128) * NL;
    __half* dst = g_vh + (size_t)head * 64 * NL;
    const int tid = threadIdx.x;
    #pragma unroll 4
    for (int i = 0; i < 64; i++) {
        int idx = tid + (i << 8);
        float4 v = ((const float4*)src)[idx];
        uint2 o;
        o.x = pack_h2(v.x, v.y);
        o.y = pack_h2(v.z, v.w);
        *(uint2*)&dst[(size_t)idx * 4] = o;
    }
}

// ---------------------------------------------------------------------------
// Flash attention, fp16 m16n8k16, register-P (C-frag == A-frag, no shuffles),
// async K/V pipeline. smem = Q(128x72h)+K(128x72h)+V(64x136h) = 54,272 B
// -> 4 CTAs/SM. All fragment LDS conflict-free (stride/2 === 4 mod 32).
// ---------------------------------------------------------------------------
#define QH 72
#define KH 72
#define VH 136
#define ATTN_SMEM ((128 * QH + 128 * KH + 64 * VH) * 2)

__global__ __launch_bounds__(256, 2) void attn_kernel() {
    extern __shared__ __half smh[];
    __half* Qs = smh;                   // 128 t x 72 (c halves)
    __half* Ks = Qs + 128 * QH;         // 128 s x 72 (c halves)
    __half* Vs = Ks + 128 * KH;         // 64 c x 136 (s halves)

    const int head = blockIdx.y;
    const int t0 = blockIdx.x << 7;
    const __half* qh = g_qh + (size_t)head * NL * 64;
    const __half* kh = g_kh + (size_t)head * NL * 64;
    const __half* vh = g_vh + (size_t)head * 64 * NL;
    const int tid  = threadIdx.x;
    const int wid  = tid >> 5;
    const int lane = tid & 31;
    const int gid  = lane >> 2;
    const int tig  = lane & 3;
    const int tb   = wid << 4;
    const int r0   = tb + gid, r1 = r0 + 8;

    const uint32_t sQ = smem_u32(Qs);
    const uint32_t sK = smem_u32(Ks);
    const uint32_t sV = smem_u32(Vs);

    // async prologue: G0 = Q + K0 (16KB each), G1 = V0 (16KB)
    #pragma unroll
    for (int i = 0; i < 4; i++) {
        int idx = tid + (i << 8);          // 0..1023
        int row = idx >> 3, j = idx & 7;
        CP_ASYNC16(sQ + (uint32_t)(row * 144 + j * 16),
                   (const char*)qh + ((size_t)(t0 + row) * 128 + j * 16));
        CP_ASYNC16(sK + (uint32_t)(row * 144 + j * 16),
                   (const char*)kh + ((size_t)row * 128 + j * 16));
    }
    CP_COMMIT();
    #pragma unroll
    for (int i = 0; i < 4; i++) {
        int idx = tid + (i << 8);
        int row = idx >> 4, j = idx & 15;
        CP_ASYNC16(sV + (uint32_t)(row * 272 + j * 16),
                   (const char*)vh + ((size_t)row * 2048 + j * 16));
    }
    CP_COMMIT();

    float m0 = -1e30f, m1 = -1e30f, l0 = 0.f, l1 = 0.f;
    float oacc[8][4];
    #pragma unroll
    for (int i = 0; i < 8; i++)
        #pragma unroll
        for (int j = 0; j < 4; j++) oacc[i][j] = 0.f;

    for (int it = 0; it < 8; it++) {
        const int s0 = it << 7;
        CP_WAIT(1);
        __syncthreads();

        // --- S = Q K^T  (fp16 m16n8k16, 4 k-steps of 16 c)
        float sacc[16][4];
        #pragma unroll
        for (int i = 0; i < 16; i++)
            #pragma unroll
            for (int j = 0; j < 4; j++) sacc[i][j] = 0.f;
        #pragma unroll
        for (int ks = 0; ks < 4; ks++) {
            const int kk = ks << 4;
            uint32_t af[4];
            af[0] = *(const uint32_t*)&Qs[(tb + gid) * QH + kk + 2 * tig];
            af[1] = *(const uint32_t*)&Qs[(tb + gid + 8) * QH + kk + 2 * tig];
            af[2] = *(const uint32_t*)&Qs[(tb + gid) * QH + kk + 8 + 2 * tig];
            af[3] = *(const uint32_t*)&Qs[(tb + gid + 8) * QH + kk + 8 + 2 * tig];
            #pragma unroll
            for (int nt = 0; nt < 16; nt++) {
                uint32_t bfr[2];
                bfr[0] = *(const uint32_t*)&Ks[(8 * nt + gid) * KH + kk + 2 * tig];
                bfr[1] = *(const uint32_t*)&Ks[(8 * nt + gid) * KH + kk + 8 + 2 * tig];
                mma_f16(sacc[nt], af, bfr);
            }
        }
        __syncthreads();

        // --- issue K(it+1)
        if (it < 7) {
            #pragma unroll
            for (int i = 0; i < 4; i++) {
                int idx = tid + (i << 8);
                int row = idx >> 3, j = idx & 7;
                CP_ASYNC16(sK + (uint32_t)(row * 144 + j * 16),
                           (const char*)kh + ((size_t)(s0 + 128 + row) * 128 + j * 16));
            }
            CP_COMMIT();
        }

        // --- online softmax (row state in registers)
        float mx0 = -1e30f, mx1 = -1e30f;
        #pragma unroll
        for (int nt = 0; nt < 16; nt++) {
            mx0 = fmaxf(mx0, fmaxf(sacc[nt][0], sacc[nt][1]));
            mx1 = fmaxf(mx1, fmaxf(sacc[nt][2], sacc[nt][3]));
        }
        mx0 = fmaxf(mx0, __shfl_xor_sync(0xffffffffu, mx0, 1));
        mx0 = fmaxf(mx0, __shfl_xor_sync(0xffffffffu, mx0, 2));
        mx1 = fmaxf(mx1, __shfl_xor_sync(0xffffffffu, mx1, 1));
        mx1 = fmaxf(mx1, __shfl_xor_sync(0xffffffffu, mx1, 2));
        float mn0 = fmaxf(m0, mx0), mn1 = fmaxf(m1, mx1);
        float sum0 = 0.f, sum1 = 0.f;
        #pragma unroll
        for (int nt = 0; nt < 16; nt++) {
            float p0 = fexp(sacc[nt][0] - mn0);
            float p1 = fexp(sacc[nt][1] - mn0);
            float p2 = fexp(sacc[nt][2] - mn1);
            float p3 = fexp(sacc[nt][3] - mn1);
            sum0 += p0 + p1; sum1 += p2 + p3;
            sacc[nt][0] = p0; sacc[nt][1] = p1;
            sacc[nt][2] = p2; sacc[nt][3] = p3;
        }
        sum0 += __shfl_xor_sync(0xffffffffu, sum0, 1);
        sum0 += __shfl_xor_sync(0xffffffffu, sum0, 2);
        sum1 += __shfl_xor_sync(0xffffffffu, sum1, 1);
        sum1 += __shfl_xor_sync(0xffffffffu, sum1, 2);
        float al0 = fexp(m0 - mn0), al1 = fexp(m1 - mn1);
        l0 = l0 * al0 + sum0;  m0 = mn0;
        l1 = l1 * al1 + sum1;  m1 = mn1;

        // --- wait V(it)
        if (it < 7) { CP_WAIT(1); } else { CP_WAIT(0); }
        __syncthreads();

        // --- O = O*alpha + P V^T : P C-frag packs directly into A-frag
        #pragma unroll
        for (int nt = 0; nt < 8; nt++) {
            oacc[nt][0] *= al0; oacc[nt][1] *= al0;
            oacc[nt][2] *= al1; oacc[nt][3] *= al1;
        }
        #pragma unroll
        for (int j = 0; j < 8; j++) {
            uint32_t pa[4];
            pa[0] = pack_h2(sacc[2 * j][0],     sacc[2 * j][1]);
            pa[1] = pack_h2(sacc[2 * j][2],     sacc[2 * j][3]);
            pa[2] = pack_h2(sacc[2 * j + 1][0], sacc[2 * j + 1][1]);
            pa[3] = pack_h2(sacc[2 * j + 1][2], sacc[2 * j + 1][3]);
            const int kk = j << 4;
            #pragma unroll
            for (int nt = 0; nt < 8; nt++) {
                int cc = (nt << 3) + gid;
                uint32_t bfr[2];
                bfr[0] = *(const uint32_t*)&Vs[cc * VH + kk + 2 * tig];
                bfr[1] = *(const uint32_t*)&Vs[cc * VH + kk + 8 + 2 * tig];
                mma_f16(oacc[nt], pa, bfr);
            }
        }
        __syncthreads();

        // --- issue V(it+1)
        if (it < 7) {
            #pragma unroll
            for (int i = 0; i < 4; i++) {
                int idx = tid + (i << 8);
                int row = idx >> 4, j = idx & 15;
                CP_ASYNC16(sV + (uint32_t)(row * 272 + j * 16),
                           (const char*)vh + ((size_t)row * 2048 +
                                              (size_t)(s0 + 128) * 2 + j * 16));
            }
            CP_COMMIT();
        }
    }

    // epilogue: divide by l, write TRANSPOSED tf32 a_t[b][t0+t][hh*64 + c]
    float inv0 = 1.0f / l0, inv1 = 1.0f / l1;
    const int bi = head >> 3, hh = head & 7;
    float* op = g_at + ((size_t)bi * NL + t0) * NC + hh * 64;
    #pragma unroll
    for (int nt = 0; nt < 8; nt++) {
        int c0 = (nt << 3) + (tig << 1);
        float2 o0, o1;
        o0.x = cvt_tf32f(oacc[nt][0] * inv0); o0.y = cvt_tf32f(oacc[nt][1] * inv0);
        o1.x = cvt_tf32f(oacc[nt][2] * inv1); o1.y = cvt_tf32f(oacc[nt][3] * inv1);
        *(float2*)&op[(size_t)r0 * NC + c0] = o0;
        *(float2*)&op[(size_t)r1 * NC + c0] = o1;
    }
}

// ---------------------------------------------------------------------------
extern "C" void kernel_launch(void* const* d_in, const int* in_sizes, int n_in,
                              void* d_out, int out_size) {
    const float* x     = (const float*)d_in[0];
    const float* nw    = (const float*)d_in[1];
    const float* nb    = (const float*)d_in[2];
    const float* wqkv  = (const float*)d_in[3];
    const float* bqkv  = (const float*)d_in[4];
    const float* wproj = (const float*)d_in[5];
    const float* bproj = (const float*)d_in[6];
    float* out = (float*)d_out;

    float *pht, *pq, *pat, *pwt, *pbq;
    cudaGetSymbolAddress((void**)&pht, g_ht);
    cudaGetSymbolAddress((void**)&pq,  g_qkv);
    cudaGetSymbolAddress((void**)&pat, g_at);
    cudaGetSymbolAddress((void**)&pwt, g_wt);
    cudaGetSymbolAddress((void**)&pbq, g_bq);

    cvt_w_kernel<<<768, 256>>>(wqkv,  pwt,                    NO3 * NC / 4, 1);
    cvt_w_kernel<<<256, 256>>>(wproj, pwt + (size_t)NO3 * NC, NC * NC / 4, 0);
    bias_q_kernel<<<6, 256>>>(bqkv);
    gn_kernel<<<512, 256>>>(x, nw, nb);

    cudaFuncSetAttribute(tc_gemm,
                         cudaFuncAttributeMaxDynamicSharedMemorySize, GEMM_SMEM);
    tc_gemm<<<dim3(8, 12, 16), 256, GEMM_SMEM>>>(pwt, pbq, pht, pq, NO3, 1);

    qk_pack<<<dim3(8, 128, 2), 256>>>();
    v_pack<<<128, 256>>>();

    cudaFuncSetAttribute(attn_kernel,
                         cudaFuncAttributeMaxDynamicSharedMemorySize, ATTN_SMEM);
    attn_kernel<<<dim3(8, 128), 256, ATTN_SMEM>>>();

    tc_gemm<<<dim3(8, 4, 16), 256, GEMM_SMEM>>>(pwt + (size_t)NO3 * NC, bproj,
                                                pat, out, NC, 0);
}

// round 16
// speedup vs baseline: 1.4245x; 1.1169x over previous
#include <cuda_runtime.h>
#include <cuda_fp16.h>
#include <cstdint>
#include <math.h>

// Problem constants: B=16, C=512, L=1024 (32x32), 32 groups, 8 heads, ch=64.
#define NB   16
#define NC   512
#define NL   1024
#define NO3  1536

// Scratch (device globals; no allocation allowed)
__device__ __half g_hth[(size_t)NB * NL * NC];    // groupnorm out, [b][l][c], fp16
__device__ float  g_qkv[(size_t)NB * NO3 * NL];   // [b][o][l], fp32 (Q pre-scaled)
__device__ __half g_ath[(size_t)NB * NL * NC];    // attention out, [b][l][c], fp16
__device__ __half g_wth[(size_t)(NO3 + NC) * NC]; // weights fp16 (Q rows pre-scaled)
__device__ float  g_bq [NO3];                     // qkv bias, Q rows pre-scaled
__device__ __half g_qh [(size_t)128 * NL * 64];   // Q fp16, [head][l][c]
__device__ __half g_kh [(size_t)128 * NL * 64];   // K fp16, [head][s][c]
__device__ __half g_vh [(size_t)128 * 64 * NL];   // V fp16, [head][c][s]

// ===========================================================================
// helpers
// ===========================================================================
__device__ __forceinline__ void mma_f16(float* d, const uint32_t* a,
                                        const uint32_t* b) {
    asm volatile(
        "mma.sync.aligned.m16n8k16.row.col.f32.f16.f16.f32 "
        "{%0,%1,%2,%3}, {%4,%5,%6,%7}, {%8,%9}, {%0,%1,%2,%3};"
        : "+f"(d[0]), "+f"(d[1]), "+f"(d[2]), "+f"(d[3])
        : "r"(a[0]), "r"(a[1]), "r"(a[2]), "r"(a[3]), "r"(b[0]), "r"(b[1]));
}
__device__ __forceinline__ uint32_t pack_h2(float lo, float hi) {
    uint32_t d;
    asm("cvt.rn.f16x2.f32 %0, %1, %2;" : "=r"(d) : "f"(hi), "f"(lo));
    return d;
}
#define CP_ASYNC16(dst, src) \
    asm volatile("cp.async.cg.shared.global [%0], [%1], 16;" \
                 :: "r"(dst), "l"(src) : "memory")
#define CP_COMMIT() asm volatile("cp.async.commit_group;" ::: "memory")
#define CP_WAIT(n)  asm volatile("cp.async.wait_group %0;" :: "n"(n) : "memory")

__device__ __forceinline__ uint32_t smem_u32(const void* p) {
    uint32_t a;
    asm("{ .reg .u64 t; cvta.to.shared.u64 t, %1; cvt.u32.u64 %0, t; }"
        : "=r"(a) : "l"(p));
    return a;
}

// fast exp on FMA pipe. x <= 0 expected.
__device__ __forceinline__ float fexp(float x) {
    float y = x * 1.4426950408889634f;
    y = fmaxf(y, -125.0f);
    int   e = __float2int_rd(y);
    float f = y - (float)e;
    float p = fmaf(0.0013333558f, f, 0.0096181291f);
    p = fmaf(p, f, 0.0555041087f);
    p = fmaf(p, f, 0.2402264758f);
    p = fmaf(p, f, 0.6931471806f);
    p = fmaf(p, f, 1.0f);
    return p * __int_as_float((e + 127) << 23);
}

// ---------------------------------------------------------------------------
// Convert weights fp32 -> fp16; optionally scale Q rows (row%192<64) by 0.125.
// ---------------------------------------------------------------------------
__global__ __launch_bounds__(256) void cvt_w_kernel(const float* __restrict__ src,
                                                    __half* __restrict__ dst,
                                                    int n4, int qmode) {
    int i = blockIdx.x * 256 + threadIdx.x;
    if (i < n4) {
        float s = 1.0f;
        if (qmode) {
            int row = i >> 7;                 // NC/4 = 128 float4 per row
            s = ((row % 192) < 64) ? 0.125f : 1.0f;
        }
        float4 v = ((const float4*)src)[i];
        uint2 o;
        o.x = pack_h2(v.x * s, v.y * s);
        o.y = pack_h2(v.z * s, v.w * s);
        ((uint2*)dst)[i] = o;
    }
}

__global__ __launch_bounds__(256) void bias_q_kernel(const float* __restrict__ b) {
    int i = blockIdx.x * 256 + threadIdx.x;
    if (i < NO3) g_bq[i] = b[i] * (((i % 192) < 64) ? 0.125f : 1.0f);
}

// ---------------------------------------------------------------------------
// GroupNorm: coalesced both ways (R11 pattern); writes fp16 h_t[b][l][c].
// ---------------------------------------------------------------------------
__global__ __launch_bounds__(256) void gn_kernel(const float* __restrict__ x,
                                                 const float* __restrict__ w,
                                                 const float* __restrict__ b) {
    const int blk = blockIdx.x;
    const int bi  = blk >> 5;
    const int g   = blk & 31;
    const int cb  = g << 4;
    const float* xg = x + ((size_t)bi * NC + (size_t)cb) * NL;
    const int tid = threadIdx.x;

    float s = 0.f, s2 = 0.f;
    for (int v = tid; v < 4096; v += 256) {
        float4 q = *(const float4*)(xg + (size_t)v * 4);
        s  += q.x + q.y + q.z + q.w;
        s2 += q.x*q.x + q.y*q.y + q.z*q.z + q.w*q.w;
    }
    #pragma unroll
    for (int d = 16; d; d >>= 1) {
        s  += __shfl_xor_sync(0xffffffffu, s,  d);
        s2 += __shfl_xor_sync(0xffffffffu, s2, d);
    }
    __shared__ float rs[8], rs2[8];
    __shared__ float smean, srstd;
    if ((tid & 31) == 0) { rs[tid >> 5] = s; rs2[tid >> 5] = s2; }
    __syncthreads();
    if (tid == 0) {
        float ts = 0.f, ts2 = 0.f;
        #pragma unroll
        for (int i = 0; i < 8; i++) { ts += rs[i]; ts2 += rs2[i]; }
        float mean = ts * (1.0f / 16384.0f);
        float var  = ts2 * (1.0f / 16384.0f) - mean * mean;
        smean = mean;
        srstd = rsqrtf(var + 1e-5f);
    }
    __syncthreads();
    const float mean = smean, rstd = srstd;

    const int cq = (tid & 3) << 2;
    const int lb = tid >> 2;
    float wc[4], bc[4];
    const float* xr[4];
    #pragma unroll
    for (int i = 0; i < 4; i++) {
        wc[i] = w[cb + cq + i] * rstd;
        bc[i] = b[cb + cq + i];
        xr[i] = x + ((size_t)bi * NC + cb + cq + i) * NL;
    }
    __half* ob = g_hth + (size_t)bi * NL * NC + cb + cq;
    #pragma unroll
    for (int it = 0; it < 16; it++) {
        const int l = lb + (it << 6);
        uint2 o;
        o.x = pack_h2((xr[0][l] - mean) * wc[0] + bc[0],
                      (xr[1][l] - mean) * wc[1] + bc[1]);
        o.y = pack_h2((xr[2][l] - mean) * wc[2] + bc[2],
                      (xr[3][l] - mean) * wc[3] + bc[3]);
        *(uint2*)&ob[(size_t)l * NC] = o;
    }
}

// ---------------------------------------------------------------------------
// fp16 m16n8k16 GEMM + bias (fp32 accum/out).
//   Y[bz][m][n] = sum_k W[m][k] * Xt[bz][n][k] + bias[m]
// 128x128 tile, BK=32 halves, 8 warps, cp.async double buffer.
// smem row stride 40 halves (20 words): 20*gid+tig spans all 32 banks ->
// every fragment LDS conflict-free; 64B payload + 16B pad per row.
// ---------------------------------------------------------------------------
#define SH 40
#define TILEH (128 * SH)
#define GEMM_SMEM (4 * TILEH * 2)             // 40960 B

__global__ __launch_bounds__(256, 2) void tc_gemm(const __half* __restrict__ W,
                                                  const float* __restrict__ bias,
                                                  const __half* __restrict__ Xt,
                                                  float* __restrict__ Y,
                                                  int M) {
    extern __shared__ char smc[];
    __half* smh = (__half*)smc;
    const int tid  = threadIdx.x;
    const int wid  = tid >> 5;
    const int lane = tid & 31;
    const int gid  = lane >> 2;
    const int tig  = lane & 3;
    const int K    = NC;
    const int n_blk = blockIdx.x << 7;
    const int m_blk = blockIdx.y << 7;
    const __half* Xb = Xt + (size_t)blockIdx.z * NL * K;
    float*        Yb = Y  + (size_t)blockIdx.z * M * NL;
    const int wm = (wid >> 1) << 5;
    const int wn = (wid & 1) << 6;

    const int lrow = tid >> 2;                  // 0..63 (+64 per i)
    const int lj   = (tid & 3) << 3;            // half offset: 0,8,16,24
    const uint32_t sbase = smem_u32(smh);

    float acc[2][8][4];
    #pragma unroll
    for (int a = 0; a < 2; a++)
        #pragma unroll
        for (int b = 0; b < 8; b++)
            #pragma unroll
            for (int c = 0; c < 4; c++) acc[a][b][c] = 0.f;

    const int nkt = K / 32;                     // 16
    {
        #pragma unroll
        for (int i = 0; i < 2; i++) {
            int row = lrow + (i << 6);
            uint32_t da = sbase + (row * SH + lj) * 2;
            uint32_t db = da + TILEH * 2;
            CP_ASYNC16(da, W  + (size_t)(m_blk + row) * K + lj);
            CP_ASYNC16(db, Xb + (size_t)(n_blk + row) * K + lj);
        }
        CP_COMMIT();
    }

    for (int kt = 0; kt < nkt; kt++) {
        const int bf = kt & 1;
        if (kt + 1 < nkt) {
            const int k0 = (kt + 1) << 5;
            uint32_t base = sbase + (((kt + 1) & 1) ? 2 * TILEH * 2 : 0);
            #pragma unroll
            for (int i = 0; i < 2; i++) {
                int row = lrow + (i << 6);
                uint32_t da = base + (row * SH + lj) * 2;
                uint32_t db = da + TILEH * 2;
                CP_ASYNC16(da, W  + (size_t)(m_blk + row) * K + k0 + lj);
                CP_ASYNC16(db, Xb + (size_t)(n_blk + row) * K + k0 + lj);
            }
            CP_COMMIT();
            CP_WAIT(1);
        } else {
            CP_WAIT(0);
        }
        __syncthreads();

        const __half* As = smh + (bf ? 2 * TILEH : 0);
        const __half* Bs = As + TILEH;
        #pragma unroll
        for (int ks = 0; ks < 2; ks++) {
            const int kk = ks << 4;
            uint32_t af[2][4];
            #pragma unroll
            for (int mt = 0; mt < 2; mt++) {
                int r0 = wm + (mt << 4) + gid;
                af[mt][0] = *(const uint32_t*)&As[r0 * SH + kk + 2 * tig];
                af[mt][1] = *(const uint32_t*)&As[(r0 + 8) * SH + kk + 2 * tig];
                af[mt][2] = *(const uint32_t*)&As[r0 * SH + kk + 8 + 2 * tig];
                af[mt][3] = *(const uint32_t*)&As[(r0 + 8) * SH + kk + 8 + 2 * tig];
            }
            #pragma unroll
            for (int nt = 0; nt < 8; nt++) {
                int n0 = wn + (nt << 3) + gid;
                uint32_t bfr[2];
                bfr[0] = *(const uint32_t*)&Bs[n0 * SH + kk + 2 * tig];
                bfr[1] = *(const uint32_t*)&Bs[n0 * SH + kk + 8 + 2 * tig];
                mma_f16(acc[0][nt], af[0], bfr);
                mma_f16(acc[1][nt], af[1], bfr);
            }
        }
        __syncthreads();
    }

    #pragma unroll
    for (int mt = 0; mt < 2; mt++) {
        int m = m_blk + wm + (mt << 4) + gid;
        float bv0 = bias[m], bv1 = bias[m + 8];
        #pragma unroll
        for (int nt = 0; nt < 8; nt++) {
            int n = n_blk + wn + (nt << 3) + (tig << 1);
            float2 o0, o1;
            o0.x = acc[mt][nt][0] + bv0; o0.y = acc[mt][nt][1] + bv0;
            o1.x = acc[mt][nt][2] + bv1; o1.y = acc[mt][nt][3] + bv1;
            *(float2*)&Yb[(size_t)m * NL + n]       = o0;
            *(float2*)&Yb[(size_t)(m + 8) * NL + n] = o1;
        }
    }
}

// ---------------------------------------------------------------------------
// Repack Q/K: g_qkv fp32 [c][l] -> fp16 [l][c] per head (transpose via smem).
// ---------------------------------------------------------------------------
__global__ __launch_bounds__(256) void qk_pack() {
    const int l0   = blockIdx.x << 7;
    const int head = blockIdx.y;
    const int z    = blockIdx.z;
    const int bi = head >> 3, hh = head & 7;
    const float* src = g_qkv + ((size_t)bi * NO3 + hh * 192 + (z ? 64 : 0)) * NL;
    __half* dst = (z ? g_kh : g_qh) + (size_t)head * NL * 64;
    __shared__ __half sh[128 * 72];
    const int tid = threadIdx.x;

    #pragma unroll
    for (int i = 0; i < 8; i++) {
        int idx = tid + (i << 8);
        int c   = idx >> 5;
        int jj  = (idx & 31) << 2;
        float4 v = *(const float4*)&src[(size_t)c * NL + l0 + jj];
        sh[(jj + 0) * 72 + c] = __float2half_rn(v.x);
        sh[(jj + 1) * 72 + c] = __float2half_rn(v.y);
        sh[(jj + 2) * 72 + c] = __float2half_rn(v.z);
        sh[(jj + 3) * 72 + c] = __float2half_rn(v.w);
    }
    __syncthreads();
    #pragma unroll
    for (int i = 0; i < 4; i++) {
        int idx = tid + (i << 8);
        int row = idx >> 3, j = idx & 7;
        uint4 v = *(const uint4*)&sh[row * 72 + j * 8];
        *(uint4*)&dst[((size_t)(l0 + row)) * 64 + j * 8] = v;
    }
}

// ---------------------------------------------------------------------------
// Repack V: g_qkv fp32 [c][l] -> fp16 [c][l] per head.
// ---------------------------------------------------------------------------
__global__ __launch_bounds__(256) void v_pack() {
    const int head = blockIdx.x;
    const int bi = head >> 3, hh = head & 7;
    const float* src = g_qkv + ((size_t)bi * NO3 + hh * 192 + 128) * NL;
    __half* dst = g_vh + (size_t)head * 64 * NL;
    const int tid = threadIdx.x;
    #pragma unroll 4
    for (int i = 0; i < 64; i++) {
        int idx = tid + (i << 8);
        float4 v = ((const float4*)src)[idx];
        uint2 o;
        o.x = pack_h2(v.x, v.y);
        o.y = pack_h2(v.z, v.w);
        *(uint2*)&dst[(size_t)idx * 4] = o;
    }
}

// ---------------------------------------------------------------------------
// Flash attention, fp16 m16n8k16, register-P, async K/V pipeline (R15,
// confirmed). Epilogue now writes fp16 a_t[b][l][c] (half2).
// ---------------------------------------------------------------------------
#define QH 72
#define KH 72
#define VH 136
#define ATTN_SMEM ((128 * QH + 128 * KH + 64 * VH) * 2)

__global__ __launch_bounds__(256, 2) void attn_kernel() {
    extern __shared__ __half smh[];
    __half* Qs = smh;
    __half* Ks = Qs + 128 * QH;
    __half* Vs = Ks + 128 * KH;

    const int head = blockIdx.y;
    const int t0 = blockIdx.x << 7;
    const __half* qh = g_qh + (size_t)head * NL * 64;
    const __half* kh = g_kh + (size_t)head * NL * 64;
    const __half* vh = g_vh + (size_t)head * 64 * NL;
    const int tid  = threadIdx.x;
    const int wid  = tid >> 5;
    const int lane = tid & 31;
    const int gid  = lane >> 2;
    const int tig  = lane & 3;
    const int tb   = wid << 4;
    const int r0   = tb + gid, r1 = r0 + 8;

    const uint32_t sQ = smem_u32(Qs);
    const uint32_t sK = smem_u32(Ks);
    const uint32_t sV = smem_u32(Vs);

    #pragma unroll
    for (int i = 0; i < 4; i++) {
        int idx = tid + (i << 8);
        int row = idx >> 3, j = idx & 7;
        CP_ASYNC16(sQ + (uint32_t)(row * 144 + j * 16),
                   (const char*)qh + ((size_t)(t0 + row) * 128 + j * 16));
        CP_ASYNC16(sK + (uint32_t)(row * 144 + j * 16),
                   (const char*)kh + ((size_t)row * 128 + j * 16));
    }
    CP_COMMIT();
    #pragma unroll
    for (int i = 0; i < 4; i++) {
        int idx = tid + (i << 8);
        int row = idx >> 4, j = idx & 15;
        CP_ASYNC16(sV + (uint32_t)(row * 272 + j * 16),
                   (const char*)vh + ((size_t)row * 2048 + j * 16));
    }
    CP_COMMIT();

    float m0 = -1e30f, m1 = -1e30f, l0 = 0.f, l1 = 0.f;
    float oacc[8][4];
    #pragma unroll
    for (int i = 0; i < 8; i++)
        #pragma unroll
        for (int j = 0; j < 4; j++) oacc[i][j] = 0.f;

    for (int it = 0; it < 8; it++) {
        const int s0 = it << 7;
        CP_WAIT(1);
        __syncthreads();

        float sacc[16][4];
        #pragma unroll
        for (int i = 0; i < 16; i++)
            #pragma unroll
            for (int j = 0; j < 4; j++) sacc[i][j] = 0.f;
        #pragma unroll
        for (int ks = 0; ks < 4; ks++) {
            const int kk = ks << 4;
            uint32_t af[4];
            af[0] = *(const uint32_t*)&Qs[(tb + gid) * QH + kk + 2 * tig];
            af[1] = *(const uint32_t*)&Qs[(tb + gid + 8) * QH + kk + 2 * tig];
            af[2] = *(const uint32_t*)&Qs[(tb + gid) * QH + kk + 8 + 2 * tig];
            af[3] = *(const uint32_t*)&Qs[(tb + gid + 8) * QH + kk + 8 + 2 * tig];
            #pragma unroll
            for (int nt = 0; nt < 16; nt++) {
                uint32_t bfr[2];
                bfr[0] = *(const uint32_t*)&Ks[(8 * nt + gid) * KH + kk + 2 * tig];
                bfr[1] = *(const uint32_t*)&Ks[(8 * nt + gid) * KH + kk + 8 + 2 * tig];
                mma_f16(sacc[nt], af, bfr);
            }
        }
        __syncthreads();

        if (it < 7) {
            #pragma unroll
            for (int i = 0; i < 4; i++) {
                int idx = tid + (i << 8);
                int row = idx >> 3, j = idx & 7;
                CP_ASYNC16(sK + (uint32_t)(row * 144 + j * 16),
                           (const char*)kh + ((size_t)(s0 + 128 + row) * 128 + j * 16));
            }
            CP_COMMIT();
        }

        float mx0 = -1e30f, mx1 = -1e30f;
        #pragma unroll
        for (int nt = 0; nt < 16; nt++) {
            mx0 = fmaxf(mx0, fmaxf(sacc[nt][0], sacc[nt][1]));
            mx1 = fmaxf(mx1, fmaxf(sacc[nt][2], sacc[nt][3]));
        }
        mx0 = fmaxf(mx0, __shfl_xor_sync(0xffffffffu, mx0, 1));
        mx0 = fmaxf(mx0, __shfl_xor_sync(0xffffffffu, mx0, 2));
        mx1 = fmaxf(mx1, __shfl_xor_sync(0xffffffffu, mx1, 1));
        mx1 = fmaxf(mx1, __shfl_xor_sync(0xffffffffu, mx1, 2));
        float mn0 = fmaxf(m0, mx0), mn1 = fmaxf(m1, mx1);
        float sum0 = 0.f, sum1 = 0.f;
        #pragma unroll
        for (int nt = 0; nt < 16; nt++) {
            float p0 = fexp(sacc[nt][0] - mn0);
            float p1 = fexp(sacc[nt][1] - mn0);
            float p2 = fexp(sacc[nt][2] - mn1);
            float p3 = fexp(sacc[nt][3] - mn1);
            sum0 += p0 + p1; sum1 += p2 + p3;
            sacc[nt][0] = p0; sacc[nt][1] = p1;
            sacc[nt][2] = p2; sacc[nt][3] = p3;
        }
        sum0 += __shfl_xor_sync(0xffffffffu, sum0, 1);
        sum0 += __shfl_xor_sync(0xffffffffu, sum0, 2);
        sum1 += __shfl_xor_sync(0xffffffffu, sum1, 1);
        sum1 += __shfl_xor_sync(0xffffffffu, sum1, 2);
        float al0 = fexp(m0 - mn0), al1 = fexp(m1 - mn1);
        l0 = l0 * al0 + sum0;  m0 = mn0;
        l1 = l1 * al1 + sum1;  m1 = mn1;

        if (it < 7) { CP_WAIT(1); } else { CP_WAIT(0); }
        __syncthreads();

        #pragma unroll
        for (int nt = 0; nt < 8; nt++) {
            oacc[nt][0] *= al0; oacc[nt][1] *= al0;
            oacc[nt][2] *= al1; oacc[nt][3] *= al1;
        }
        #pragma unroll
        for (int j = 0; j < 8; j++) {
            uint32_t pa[4];
            pa[0] = pack_h2(sacc[2 * j][0],     sacc[2 * j][1]);
            pa[1] = pack_h2(sacc[2 * j][2],     sacc[2 * j][3]);
            pa[2] = pack_h2(sacc[2 * j + 1][0], sacc[2 * j + 1][1]);
            pa[3] = pack_h2(sacc[2 * j + 1][2], sacc[2 * j + 1][3]);
            const int kk = j << 4;
            #pragma unroll
            for (int nt = 0; nt < 8; nt++) {
                int cc = (nt << 3) + gid;
                uint32_t bfr[2];
                bfr[0] = *(const uint32_t*)&Vs[cc * VH + kk + 2 * tig];
                bfr[1] = *(const uint32_t*)&Vs[cc * VH + kk + 8 + 2 * tig];
                mma_f16(oacc[nt], pa, bfr);
            }
        }
        __syncthreads();

        if (it < 7) {
            #pragma unroll
            for (int i = 0; i < 4; i++) {
                int idx = tid + (i << 8);
                int row = idx >> 4, j = idx & 15;
                CP_ASYNC16(sV + (uint32_t)(row * 272 + j * 16),
                           (const char*)vh + ((size_t)row * 2048 +
                                              (size_t)(s0 + 128) * 2 + j * 16));
            }
            CP_COMMIT();
        }
    }

    // epilogue: divide by l, write fp16 a_t[b][t0+t][hh*64 + c]
    float inv0 = 1.0f / l0, inv1 = 1.0f / l1;
    const int bi = head >> 3, hh = head & 7;
    __half* op = g_ath + ((size_t)bi * NL + t0) * NC + hh * 64;
    #pragma unroll
    for (int nt = 0; nt < 8; nt++) {
        int c0 = (nt << 3) + (tig << 1);
        uint32_t o0 = pack_h2(oacc[nt][0] * inv0, oacc[nt][1] * inv0);
        uint32_t o1 = pack_h2(oacc[nt][2] * inv1, oacc[nt][3] * inv1);
        *(uint32_t*)&op[(size_t)r0 * NC + c0] = o0;
        *(uint32_t*)&op[(size_t)r1 * NC + c0] = o1;
    }
}

// ---------------------------------------------------------------------------
extern "C" void kernel_launch(void* const* d_in, const int* in_sizes, int n_in,
                              void* d_out, int out_size) {
    const float* x     = (const float*)d_in[0];
    const float* nw    = (const float*)d_in[1];
    const float* nb    = (const float*)d_in[2];
    const float* wqkv  = (const float*)d_in[3];
    const float* bqkv  = (const float*)d_in[4];
    const float* wproj = (const float*)d_in[5];
    const float* bproj = (const float*)d_in[6];
    float* out = (float*)d_out;

    __half *phth, *path, *pwth;
    float  *pq, *pbq;
    cudaGetSymbolAddress((void**)&phth, g_hth);
    cudaGetSymbolAddress((void**)&pq,   g_qkv);
    cudaGetSymbolAddress((void**)&path, g_ath);
    cudaGetSymbolAddress((void**)&pwth, g_wth);
    cudaGetSymbolAddress((void**)&pbq,  g_bq);

    cvt_w_kernel<<<768, 256>>>(wqkv,  pwth,                    NO3 * NC / 4, 1);
    cvt_w_kernel<<<256, 256>>>(wproj, pwth + (size_t)NO3 * NC, NC * NC / 4, 0);
    bias_q_kernel<<<6, 256>>>(bqkv);
    gn_kernel<<<512, 256>>>(x, nw, nb);

    cudaFuncSetAttribute(tc_gemm,
                         cudaFuncAttributeMaxDynamicSharedMemorySize, GEMM_SMEM);
    tc_gemm<<<dim3(8, 12, 16), 256, GEMM_SMEM>>>(pwth, pbq, phth, pq, NO3);

    qk_pack<<<dim3(8, 128, 2), 256>>>();
    v_pack<<<128, 256>>>();

    cudaFuncSetAttribute(attn_kernel,
                         cudaFuncAttributeMaxDynamicSharedMemorySize, ATTN_SMEM);
    attn_kernel<<<dim3(8, 128), 256, ATTN_SMEM>>>();

    tc_gemm<<<dim3(8, 4, 16), 256, GEMM_SMEM>>>(pwth + (size_t)NO3 * NC, bproj,
                                                path, out, NC);
}

// round 17
// speedup vs baseline: 1.6732x; 1.1746x over previous
#include <cuda_runtime.h>
#include <cuda_fp16.h>
#include <cstdint>
#include <math.h>

// Problem constants: B=16, C=512, L=1024 (32x32), 32 groups, 8 heads, ch=64.
#define NB   16
#define NC   512
#define NL   1024
#define NO3  1536

// Scratch (device globals; no allocation allowed)
__device__ __half g_hth[(size_t)NB * NL * NC];    // groupnorm out, [b][l][c], fp16
__device__ __half g_ath[(size_t)NB * NL * NC];    // attention out, [b][l][c], fp16
__device__ __half g_wth[(size_t)(NO3 + NC) * NC]; // weights fp16 (Q rows pre-scaled)
__device__ float  g_bq [NO3];                     // qkv bias, Q rows pre-scaled
__device__ __half g_qh [(size_t)128 * NL * 64];   // Q fp16, [head][l][c]
__device__ __half g_kh [(size_t)128 * NL * 64];   // K fp16, [head][s][c]
__device__ __half g_vh [(size_t)128 * 64 * NL];   // V fp16, [head][c][s]

// ===========================================================================
// helpers
// ===========================================================================
__device__ __forceinline__ void mma_f16(float* d, const uint32_t* a,
                                        const uint32_t* b) {
    asm volatile(
        "mma.sync.aligned.m16n8k16.row.col.f32.f16.f16.f32 "
        "{%0,%1,%2,%3}, {%4,%5,%6,%7}, {%8,%9}, {%0,%1,%2,%3};"
        : "+f"(d[0]), "+f"(d[1]), "+f"(d[2]), "+f"(d[3])
        : "r"(a[0]), "r"(a[1]), "r"(a[2]), "r"(a[3]), "r"(b[0]), "r"(b[1]));
}
__device__ __forceinline__ uint32_t pack_h2(float lo, float hi) {
    uint32_t d;
    asm("cvt.rn.f16x2.f32 %0, %1, %2;" : "=r"(d) : "f"(hi), "f"(lo));
    return d;
}
#define CP_ASYNC16(dst, src) \
    asm volatile("cp.async.cg.shared.global [%0], [%1], 16;" \
                 :: "r"(dst), "l"(src) : "memory")
#define CP_COMMIT() asm volatile("cp.async.commit_group;" ::: "memory")
#define CP_WAIT(n)  asm volatile("cp.async.wait_group %0;" :: "n"(n) : "memory")

__device__ __forceinline__ uint32_t smem_u32(const void* p) {
    uint32_t a;
    asm("{ .reg .u64 t; cvta.to.shared.u64 t, %1; cvt.u32.u64 %0, t; }"
        : "=r"(a) : "l"(p));
    return a;
}

// fast exp on FMA pipe. x <= 0 expected.
__device__ __forceinline__ float fexp(float x) {
    float y = x * 1.4426950408889634f;
    y = fmaxf(y, -125.0f);
    int   e = __float2int_rd(y);
    float f = y - (float)e;
    float p = fmaf(0.0013333558f, f, 0.0096181291f);
    p = fmaf(p, f, 0.0555041087f);
    p = fmaf(p, f, 0.2402264758f);
    p = fmaf(p, f, 0.6931471806f);
    p = fmaf(p, f, 1.0f);
    return p * __int_as_float((e + 127) << 23);
}

// ---------------------------------------------------------------------------
// Convert weights fp32 -> fp16; optionally scale Q rows (row%192<64) by 0.125.
// ---------------------------------------------------------------------------
__global__ __launch_bounds__(256) void cvt_w_kernel(const float* __restrict__ src,
                                                    __half* __restrict__ dst,
                                                    int n4, int qmode) {
    int i = blockIdx.x * 256 + threadIdx.x;
    if (i < n4) {
        float s = 1.0f;
        if (qmode) {
            int row = i >> 7;
            s = ((row % 192) < 64) ? 0.125f : 1.0f;
        }
        float4 v = ((const float4*)src)[i];
        uint2 o;
        o.x = pack_h2(v.x * s, v.y * s);
        o.y = pack_h2(v.z * s, v.w * s);
        ((uint2*)dst)[i] = o;
    }
}

__global__ __launch_bounds__(256) void bias_q_kernel(const float* __restrict__ b) {
    int i = blockIdx.x * 256 + threadIdx.x;
    if (i < NO3) g_bq[i] = b[i] * (((i % 192) < 64) ? 0.125f : 1.0f);
}

// ---------------------------------------------------------------------------
// GroupNorm: coalesced both ways; writes fp16 h_t[b][l][c]. (R16, confirmed)
// ---------------------------------------------------------------------------
__global__ __launch_bounds__(256) void gn_kernel(const float* __restrict__ x,
                                                 const float* __restrict__ w,
                                                 const float* __restrict__ b) {
    const int blk = blockIdx.x;
    const int bi  = blk >> 5;
    const int g   = blk & 31;
    const int cb  = g << 4;
    const float* xg = x + ((size_t)bi * NC + (size_t)cb) * NL;
    const int tid = threadIdx.x;

    float s = 0.f, s2 = 0.f;
    for (int v = tid; v < 4096; v += 256) {
        float4 q = *(const float4*)(xg + (size_t)v * 4);
        s  += q.x + q.y + q.z + q.w;
        s2 += q.x*q.x + q.y*q.y + q.z*q.z + q.w*q.w;
    }
    #pragma unroll
    for (int d = 16; d; d >>= 1) {
        s  += __shfl_xor_sync(0xffffffffu, s,  d);
        s2 += __shfl_xor_sync(0xffffffffu, s2, d);
    }
    __shared__ float rs[8], rs2[8];
    __shared__ float smean, srstd;
    if ((tid & 31) == 0) { rs[tid >> 5] = s; rs2[tid >> 5] = s2; }
    __syncthreads();
    if (tid == 0) {
        float ts = 0.f, ts2 = 0.f;
        #pragma unroll
        for (int i = 0; i < 8; i++) { ts += rs[i]; ts2 += rs2[i]; }
        float mean = ts * (1.0f / 16384.0f);
        float var  = ts2 * (1.0f / 16384.0f) - mean * mean;
        smean = mean;
        srstd = rsqrtf(var + 1e-5f);
    }
    __syncthreads();
    const float mean = smean, rstd = srstd;

    const int cq = (tid & 3) << 2;
    const int lb = tid >> 2;
    float wc[4], bc[4];
    const float* xr[4];
    #pragma unroll
    for (int i = 0; i < 4; i++) {
        wc[i] = w[cb + cq + i] * rstd;
        bc[i] = b[cb + cq + i];
        xr[i] = x + ((size_t)bi * NC + cb + cq + i) * NL;
    }
    __half* ob = g_hth + (size_t)bi * NL * NC + cb + cq;
    #pragma unroll
    for (int it = 0; it < 16; it++) {
        const int l = lb + (it << 6);
        uint2 o;
        o.x = pack_h2((xr[0][l] - mean) * wc[0] + bc[0],
                      (xr[1][l] - mean) * wc[1] + bc[1]);
        o.y = pack_h2((xr[2][l] - mean) * wc[2] + bc[2],
                      (xr[3][l] - mean) * wc[3] + bc[3]);
        *(uint2*)&ob[(size_t)l * NC] = o;
    }
}

// ---------------------------------------------------------------------------
// fp16 m16n8k16 GEMM + bias. mode 0: fp32 out Y[bz][m][n] (proj).
// mode 1 (QKV): write DIRECTLY into attention layouts — each warp's 32-row
// block lies in exactly one Q/K/V segment of one head (32 | 64-aligned segs):
//   V warps: acc is already [c][l] -> direct half2 stores to g_vh.
//   Q/K warps: per-warp smem transpose (reuse operand buffers after the
//   final mainloop barrier; 5120 B/warp, stride 40 halves) -> uint4 stores
//   to g_qh/g_kh [l][c].
// ---------------------------------------------------------------------------
#define SH 40
#define TILEH (128 * SH)
#define GEMM_SMEM (4 * TILEH * 2)             // 40960 B

__global__ __launch_bounds__(256, 2) void tc_gemm(const __half* __restrict__ W,
                                                  const float* __restrict__ bias,
                                                  const __half* __restrict__ Xt,
                                                  float* __restrict__ Y,
                                                  int M, int mode) {
    extern __shared__ char smc[];
    __half* smh = (__half*)smc;
    const int tid  = threadIdx.x;
    const int wid  = tid >> 5;
    const int lane = tid & 31;
    const int gid  = lane >> 2;
    const int tig  = lane & 3;
    const int K    = NC;
    const int n_blk = blockIdx.x << 7;
    const int m_blk = blockIdx.y << 7;
    const __half* Xb = Xt + (size_t)blockIdx.z * NL * K;
    const int wm = (wid >> 1) << 5;
    const int wn = (wid & 1) << 6;

    const int lrow = tid >> 2;
    const int lj   = (tid & 3) << 3;
    const uint32_t sbase = smem_u32(smh);

    float acc[2][8][4];
    #pragma unroll
    for (int a = 0; a < 2; a++)
        #pragma unroll
        for (int b = 0; b < 8; b++)
            #pragma unroll
            for (int c = 0; c < 4; c++) acc[a][b][c] = 0.f;

    const int nkt = K / 32;
    {
        #pragma unroll
        for (int i = 0; i < 2; i++) {
            int row = lrow + (i << 6);
            uint32_t da = sbase + (row * SH + lj) * 2;
            uint32_t db = da + TILEH * 2;
            CP_ASYNC16(da, W  + (size_t)(m_blk + row) * K + lj);
            CP_ASYNC16(db, Xb + (size_t)(n_blk + row) * K + lj);
        }
        CP_COMMIT();
    }

    for (int kt = 0; kt < nkt; kt++) {
        const int bf = kt & 1;
        if (kt + 1 < nkt) {
            const int k0 = (kt + 1) << 5;
            uint32_t base = sbase + (((kt + 1) & 1) ? 2 * TILEH * 2 : 0);
            #pragma unroll
            for (int i = 0; i < 2; i++) {
                int row = lrow + (i << 6);
                uint32_t da = base + (row * SH + lj) * 2;
                uint32_t db = da + TILEH * 2;
                CP_ASYNC16(da, W  + (size_t)(m_blk + row) * K + k0 + lj);
                CP_ASYNC16(db, Xb + (size_t)(n_blk + row) * K + k0 + lj);
            }
            CP_COMMIT();
            CP_WAIT(1);
        } else {
            CP_WAIT(0);
        }
        __syncthreads();

        const __half* As = smh + (bf ? 2 * TILEH : 0);
        const __half* Bs = As + TILEH;
        #pragma unroll
        for (int ks = 0; ks < 2; ks++) {
            const int kk = ks << 4;
            uint32_t af[2][4];
            #pragma unroll
            for (int mt = 0; mt < 2; mt++) {
                int r0 = wm + (mt << 4) + gid;
                af[mt][0] = *(const uint32_t*)&As[r0 * SH + kk + 2 * tig];
                af[mt][1] = *(const uint32_t*)&As[(r0 + 8) * SH + kk + 2 * tig];
                af[mt][2] = *(const uint32_t*)&As[r0 * SH + kk + 8 + 2 * tig];
                af[mt][3] = *(const uint32_t*)&As[(r0 + 8) * SH + kk + 8 + 2 * tig];
            }
            #pragma unroll
            for (int nt = 0; nt < 8; nt++) {
                int n0 = wn + (nt << 3) + gid;
                uint32_t bfr[2];
                bfr[0] = *(const uint32_t*)&Bs[n0 * SH + kk + 2 * tig];
                bfr[1] = *(const uint32_t*)&Bs[n0 * SH + kk + 8 + 2 * tig];
                mma_f16(acc[0][nt], af[0], bfr);
                mma_f16(acc[1][nt], af[1], bfr);
            }
        }
        __syncthreads();   // (also: after last kt, all warps done with smem)
    }

    if (mode == 0) {
        float* Yb = Y + (size_t)blockIdx.z * M * NL;
        #pragma unroll
        for (int mt = 0; mt < 2; mt++) {
            int m = m_blk + wm + (mt << 4) + gid;
            float bv0 = bias[m], bv1 = bias[m + 8];
            #pragma unroll
            for (int nt = 0; nt < 8; nt++) {
                int n = n_blk + wn + (nt << 3) + (tig << 1);
                float2 o0, o1;
                o0.x = acc[mt][nt][0] + bv0; o0.y = acc[mt][nt][1] + bv0;
                o1.x = acc[mt][nt][2] + bv1; o1.y = acc[mt][nt][3] + bv1;
                *(float2*)&Yb[(size_t)m * NL + n]       = o0;
                *(float2*)&Yb[(size_t)(m + 8) * NL + n] = o1;
            }
        }
        return;
    }

    // ---- mode 1: fused QKV pack epilogue ----
    const int o0   = m_blk + wm;            // warp's first output row
    const int head = blockIdx.z * 8 + o0 / 192;
    const int r    = o0 % 192;
    const int seg  = r >> 6;                // 0=Q, 1=K, 2=V
    const int cbase = r & 63;

    if (seg == 2) {
        // V: [c][l] == natural [m][n]; direct half2 stores
        __half* dstv = g_vh + (size_t)head * 64 * NL;
        #pragma unroll
        for (int mt = 0; mt < 2; mt++) {
            int ml = (mt << 4) + gid;
            float bv0 = bias[o0 + ml], bv1 = bias[o0 + ml + 8];
            #pragma unroll
            for (int nt = 0; nt < 8; nt++) {
                int n = n_blk + wn + (nt << 3) + (tig << 1);
                uint32_t p0 = pack_h2(acc[mt][nt][0] + bv0, acc[mt][nt][1] + bv0);
                uint32_t p1 = pack_h2(acc[mt][nt][2] + bv1, acc[mt][nt][3] + bv1);
                *(uint32_t*)&dstv[(size_t)(cbase + ml) * NL + n]     = p0;
                *(uint32_t*)&dstv[(size_t)(cbase + ml + 8) * NL + n] = p1;
            }
        }
    } else {
        // Q/K: per-warp smem transpose into [l][c]
        __half* tr = smh + wid * 2560;      // 64 rows x 40 halves (5120 B)
        #pragma unroll
        for (int mt = 0; mt < 2; mt++) {
            int ml0 = (mt << 4) + gid;
            int ml1 = ml0 + 8;
            float bv0 = bias[o0 + ml0], bv1 = bias[o0 + ml1];
            #pragma unroll
            for (int nt = 0; nt < 8; nt++) {
                int nl = (nt << 3) + (tig << 1);
                tr[nl * SH + ml0]       = __float2half_rn(acc[mt][nt][0] + bv0);
                tr[(nl + 1) * SH + ml0] = __float2half_rn(acc[mt][nt][1] + bv0);
                tr[nl * SH + ml1]       = __float2half_rn(acc[mt][nt][2] + bv1);
                tr[(nl + 1) * SH + ml1] = __float2half_rn(acc[mt][nt][3] + bv1);
            }
        }
        __syncwarp();
        __half* dst = (seg == 0 ? g_qh : g_kh) + (size_t)head * NL * 64;
        #pragma unroll
        for (int t = 0; t < 8; t++) {
            int idx = (t << 5) + lane;
            int row = idx >> 2;             // 0..63  (local l)
            int j   = idx & 3;              // m-octet
            uint4 v = *(const uint4*)&tr[row * SH + (j << 3)];
            int l = n_blk + wn + row;
            *(uint4*)&dst[(size_t)l * 64 + cbase + (j << 3)] = v;
        }
    }
}

// ---------------------------------------------------------------------------
// Flash attention, fp16 m16n8k16, register-P, async K/V pipeline (R15/16,
// confirmed). Writes fp16 a_t[b][l][c].
// ---------------------------------------------------------------------------
#define QH 72
#define KH 72
#define VH 136
#define ATTN_SMEM ((128 * QH + 128 * KH + 64 * VH) * 2)

__global__ __launch_bounds__(256, 2) void attn_kernel() {
    extern __shared__ __half smh[];
    __half* Qs = smh;
    __half* Ks = Qs + 128 * QH;
    __half* Vs = Ks + 128 * KH;

    const int head = blockIdx.y;
    const int t0 = blockIdx.x << 7;
    const __half* qh = g_qh + (size_t)head * NL * 64;
    const __half* kh = g_kh + (size_t)head * NL * 64;
    const __half* vh = g_vh + (size_t)head * 64 * NL;
    const int tid  = threadIdx.x;
    const int wid  = tid >> 5;
    const int lane = tid & 31;
    const int gid  = lane >> 2;
    const int tig  = lane & 3;
    const int tb   = wid << 4;
    const int r0   = tb + gid, r1 = r0 + 8;

    const uint32_t sQ = smem_u32(Qs);
    const uint32_t sK = smem_u32(Ks);
    const uint32_t sV = smem_u32(Vs);

    #pragma unroll
    for (int i = 0; i < 4; i++) {
        int idx = tid + (i << 8);
        int row = idx >> 3, j = idx & 7;
        CP_ASYNC16(sQ + (uint32_t)(row * 144 + j * 16),
                   (const char*)qh + ((size_t)(t0 + row) * 128 + j * 16));
        CP_ASYNC16(sK + (uint32_t)(row * 144 + j * 16),
                   (const char*)kh + ((size_t)row * 128 + j * 16));
    }
    CP_COMMIT();
    #pragma unroll
    for (int i = 0; i < 4; i++) {
        int idx = tid + (i << 8);
        int row = idx >> 4, j = idx & 15;
        CP_ASYNC16(sV + (uint32_t)(row * 272 + j * 16),
                   (const char*)vh + ((size_t)row * 2048 + j * 16));
    }
    CP_COMMIT();

    float m0 = -1e30f, m1 = -1e30f, l0 = 0.f, l1 = 0.f;
    float oacc[8][4];
    #pragma unroll
    for (int i = 0; i < 8; i++)
        #pragma unroll
        for (int j = 0; j < 4; j++) oacc[i][j] = 0.f;

    for (int it = 0; it < 8; it++) {
        const int s0 = it << 7;
        CP_WAIT(1);
        __syncthreads();

        float sacc[16][4];
        #pragma unroll
        for (int i = 0; i < 16; i++)
            #pragma unroll
            for (int j = 0; j < 4; j++) sacc[i][j] = 0.f;
        #pragma unroll
        for (int ks = 0; ks < 4; ks++) {
            const int kk = ks << 4;
            uint32_t af[4];
            af[0] = *(const uint32_t*)&Qs[(tb + gid) * QH + kk + 2 * tig];
            af[1] = *(const uint32_t*)&Qs[(tb + gid + 8) * QH + kk + 2 * tig];
            af[2] = *(const uint32_t*)&Qs[(tb + gid) * QH + kk + 8 + 2 * tig];
            af[3] = *(const uint32_t*)&Qs[(tb + gid + 8) * QH + kk + 8 + 2 * tig];
            #pragma unroll
            for (int nt = 0; nt < 16; nt++) {
                uint32_t bfr[2];
                bfr[0] = *(const uint32_t*)&Ks[(8 * nt + gid) * KH + kk + 2 * tig];
                bfr[1] = *(const uint32_t*)&Ks[(8 * nt + gid) * KH + kk + 8 + 2 * tig];
                mma_f16(sacc[nt], af, bfr);
            }
        }
        __syncthreads();

        if (it < 7) {
            #pragma unroll
            for (int i = 0; i < 4; i++) {
                int idx = tid + (i << 8);
                int row = idx >> 3, j = idx & 7;
                CP_ASYNC16(sK + (uint32_t)(row * 144 + j * 16),
                           (const char*)kh + ((size_t)(s0 + 128 + row) * 128 + j * 16));
            }
            CP_COMMIT();
        }

        float mx0 = -1e30f, mx1 = -1e30f;
        #pragma unroll
        for (int nt = 0; nt < 16; nt++) {
            mx0 = fmaxf(mx0, fmaxf(sacc[nt][0], sacc[nt][1]));
            mx1 = fmaxf(mx1, fmaxf(sacc[nt][2], sacc[nt][3]));
        }
        mx0 = fmaxf(mx0, __shfl_xor_sync(0xffffffffu, mx0, 1));
        mx0 = fmaxf(mx0, __shfl_xor_sync(0xffffffffu, mx0, 2));
        mx1 = fmaxf(mx1, __shfl_xor_sync(0xffffffffu, mx1, 1));
        mx1 = fmaxf(mx1, __shfl_xor_sync(0xffffffffu, mx1, 2));
        float mn0 = fmaxf(m0, mx0), mn1 = fmaxf(m1, mx1);
        float sum0 = 0.f, sum1 = 0.f;
        #pragma unroll
        for (int nt = 0; nt < 16; nt++) {
            float p0 = fexp(sacc[nt][0] - mn0);
            float p1 = fexp(sacc[nt][1] - mn0);
            float p2 = fexp(sacc[nt][2] - mn1);
            float p3 = fexp(sacc[nt][3] - mn1);
            sum0 += p0 + p1; sum1 += p2 + p3;
            sacc[nt][0] = p0; sacc[nt][1] = p1;
            sacc[nt][2] = p2; sacc[nt][3] = p3;
        }
        sum0 += __shfl_xor_sync(0xffffffffu, sum0, 1);
        sum0 += __shfl_xor_sync(0xffffffffu, sum0, 2);
        sum1 += __shfl_xor_sync(0xffffffffu, sum1, 1);
        sum1 += __shfl_xor_sync(0xffffffffu, sum1, 2);
        float al0 = fexp(m0 - mn0), al1 = fexp(m1 - mn1);
        l0 = l0 * al0 + sum0;  m0 = mn0;
        l1 = l1 * al1 + sum1;  m1 = mn1;

        if (it < 7) { CP_WAIT(1); } else { CP_WAIT(0); }
        __syncthreads();

        #pragma unroll
        for (int nt = 0; nt < 8; nt++) {
            oacc[nt][0] *= al0; oacc[nt][1] *= al0;
            oacc[nt][2] *= al1; oacc[nt][3] *= al1;
        }
        #pragma unroll
        for (int j = 0; j < 8; j++) {
            uint32_t pa[4];
            pa[0] = pack_h2(sacc[2 * j][0],     sacc[2 * j][1]);
            pa[1] = pack_h2(sacc[2 * j][2],     sacc[2 * j][3]);
            pa[2] = pack_h2(sacc[2 * j + 1][0], sacc[2 * j + 1][1]);
            pa[3] = pack_h2(sacc[2 * j + 1][2], sacc[2 * j + 1][3]);
            const int kk = j << 4;
            #pragma unroll
            for (int nt = 0; nt < 8; nt++) {
                int cc = (nt << 3) + gid;
                uint32_t bfr[2];
                bfr[0] = *(const uint32_t*)&Vs[cc * VH + kk + 2 * tig];
                bfr[1] = *(const uint32_t*)&Vs[cc * VH + kk + 8 + 2 * tig];
                mma_f16(oacc[nt], pa, bfr);
            }
        }
        __syncthreads();

        if (it < 7) {
            #pragma unroll
            for (int i = 0; i < 4; i++) {
                int idx = tid + (i << 8);
                int row = idx >> 4, j = idx & 15;
                CP_ASYNC16(sV + (uint32_t)(row * 272 + j * 16),
                           (const char*)vh + ((size_t)row * 2048 +
                                              (size_t)(s0 + 128) * 2 + j * 16));
            }
            CP_COMMIT();
        }
    }

    // epilogue: divide by l, write fp16 a_t[b][t0+t][hh*64 + c]
    float inv0 = 1.0f / l0, inv1 = 1.0f / l1;
    const int bi = head >> 3, hh = head & 7;
    __half* op = g_ath + ((size_t)bi * NL + t0) * NC + hh * 64;
    #pragma unroll
    for (int nt = 0; nt < 8; nt++) {
        int c0 = (nt << 3) + (tig << 1);
        uint32_t o0 = pack_h2(oacc[nt][0] * inv0, oacc[nt][1] * inv0);
        uint32_t o1 = pack_h2(oacc[nt][2] * inv1, oacc[nt][3] * inv1);
        *(uint32_t*)&op[(size_t)r0 * NC + c0] = o0;
        *(uint32_t*)&op[(size_t)r1 * NC + c0] = o1;
    }
}

// ---------------------------------------------------------------------------
extern "C" void kernel_launch(void* const* d_in, const int* in_sizes, int n_in,
                              void* d_out, int out_size) {
    const float* x     = (const float*)d_in[0];
    const float* nw    = (const float*)d_in[1];
    const float* nb    = (const float*)d_in[2];
    const float* wqkv  = (const float*)d_in[3];
    const float* bqkv  = (const float*)d_in[4];
    const float* wproj = (const float*)d_in[5];
    const float* bproj = (const float*)d_in[6];
    float* out = (float*)d_out;

    __half *phth, *path, *pwth;
    float  *pbq;
    cudaGetSymbolAddress((void**)&phth, g_hth);
    cudaGetSymbolAddress((void**)&path, g_ath);
    cudaGetSymbolAddress((void**)&pwth, g_wth);
    cudaGetSymbolAddress((void**)&pbq,  g_bq);

    cvt_w_kernel<<<768, 256>>>(wqkv,  pwth,                    NO3 * NC / 4, 1);
    cvt_w_kernel<<<256, 256>>>(wproj, pwth + (size_t)NO3 * NC, NC * NC / 4, 0);
    bias_q_kernel<<<6, 256>>>(bqkv);
    gn_kernel<<<512, 256>>>(x, nw, nb);

    cudaFuncSetAttribute(tc_gemm,
                         cudaFuncAttributeMaxDynamicSharedMemorySize, GEMM_SMEM);
    // QKV GEMM with fused Q/K/V packing epilogue
    tc_gemm<<<dim3(8, 12, 16), 256, GEMM_SMEM>>>(pwth, pbq, phth, nullptr,
                                                 NO3, 1);

    cudaFuncSetAttribute(attn_kernel,
                         cudaFuncAttributeMaxDynamicSharedMemorySize, ATTN_SMEM);
    attn_kernel<<<dim3(8, 128), 256, ATTN_SMEM>>>();

    tc_gemm<<<dim3(8, 4, 16), 256, GEMM_SMEM>>>(pwth + (size_t)NO3 * NC, bproj,
                                                path, out, NC, 0);
}